// round 2
// baseline (speedup 1.0000x reference)
#include <cuda_runtime.h>
#include <cstdint>

#define N_NODES 100000
#define N_EDGES 1600000
#define FIN 128
#define FH 64
#define FOUT 40

// ---------------- scratch (device globals; no allocs allowed) ----------------
__device__ __align__(16) float g_h1[N_NODES * FH];   // x @ W1
__device__ __align__(16) float g_a1[N_NODES * FH];   // aggregated / activated
__device__ __align__(16) float g_h2[N_NODES * FOUT]; // a1 @ W2
__device__ int   g_deg[N_NODES];
__device__ float g_inv[N_NODES];
__device__ int   g_is64;

// ---------------- helpers ----------------
__device__ __forceinline__ void red_add_f32x4(float* p, float4 v) {
    asm volatile("red.global.add.v4.f32 [%0], {%1,%2,%3,%4};"
                 :: "l"(p), "f"(v.x), "f"(v.y), "f"(v.z), "f"(v.w) : "memory");
}

__device__ __forceinline__ int load_idx(const void* ei, int half, int e) {
    if (g_is64) return (int)((const long long*)ei)[(size_t)half * N_EDGES + e];
    return ((const int*)ei)[(size_t)half * N_EDGES + e];
}

// Threefry-2x32, 20 rounds (JAX rotation schedule)
__device__ __forceinline__ uint2 threefry2x32(uint32_t k0, uint32_t k1,
                                              uint32_t x0, uint32_t x1) {
    uint32_t ks2 = 0x1BD11BDAu ^ k0 ^ k1;
    x0 += k0; x1 += k1;
#define TF_R(r) { x0 += x1; x1 = __funnelshift_l(x1, x1, r); x1 ^= x0; }
    TF_R(13) TF_R(15) TF_R(26) TF_R(6)
    x0 += k1;  x1 += ks2 + 1u;
    TF_R(17) TF_R(29) TF_R(16) TF_R(24)
    x0 += ks2; x1 += k0 + 2u;
    TF_R(13) TF_R(15) TF_R(26) TF_R(6)
    x0 += k0;  x1 += k1 + 3u;
    TF_R(17) TF_R(29) TF_R(16) TF_R(24)
    x0 += k1;  x1 += ks2 + 4u;
    TF_R(13) TF_R(15) TF_R(26) TF_R(6)
    x0 += ks2; x1 += k0 + 5u;
#undef TF_R
    return make_uint2(x0, x1);
}

// JAX partitionable threefry bits for flat index i with key(42) = (0, 42).
__device__ __forceinline__ bool keep_mask(uint32_t i) {
    uint2 o = threefry2x32(0u, 42u, 0u, i);   // counts_hi = 0, counts_lo = i
    uint32_t bits = o.x ^ o.y;                // 32-bit output path: xor of halves
    float u = __uint_as_float((bits >> 9) | 0x3f800000u) - 1.0f;
    return u < 0.5f;
}

// ---------------- kernels ----------------
__global__ void k_detect(const long long* ei) {
    if (blockIdx.x == 0 && threadIdx.x == 0) {
        int ok = 1;
        for (int i = 0; i < 128; i++) {  // first 1KB only: safe for either dtype
            long long v = ei[i];
            if (v < 0 || v >= N_NODES) ok = 0;
        }
        g_is64 = ok;
    }
}

__global__ void k_zero_deg() {
    int i = blockIdx.x * 256 + threadIdx.x;
    if (i < N_NODES) g_deg[i] = 0;
}

__global__ void k_deg(const void* ei) {
    int e = blockIdx.x * 256 + threadIdx.x;
    if (e >= N_EDGES) return;
    int d = load_idx(ei, 1, e);
    atomicAdd(&g_deg[d], 1);
}

__global__ void k_inv() {
    int i = blockIdx.x * 256 + threadIdx.x;
    if (i < N_NODES) g_inv[i] = rsqrtf((float)g_deg[i] + 1.0f);
}

// h1 = x @ W1 ; a1 = h1 * inv^2  (self-loop init)
// block: 256 threads = 64 rows x 4 col-groups of 16 cols
__global__ void __launch_bounds__(256) k_gemm1(const float* __restrict__ x,
                                               const float* __restrict__ W1) {
    __shared__ float4 sW[FIN * 16];   // 128 x 64 floats = 32KB
    for (int idx = threadIdx.x; idx < FIN * 16; idx += 256)
        sW[idx] = ((const float4*)W1)[idx];
    __syncthreads();

    int row = blockIdx.x * 64 + (threadIdx.x >> 2);
    int cg  = threadIdx.x & 3;
    if (row >= N_NODES) return;

    const float4* xr = (const float4*)(x + (size_t)row * FIN);
    float acc[16];
#pragma unroll
    for (int i = 0; i < 16; i++) acc[i] = 0.0f;

#pragma unroll 4
    for (int k4 = 0; k4 < 32; k4++) {
        float4 xv = xr[k4];
#pragma unroll
        for (int j = 0; j < 4; j++) {
            float xs = (j == 0) ? xv.x : (j == 1) ? xv.y : (j == 2) ? xv.z : xv.w;
            int k = k4 * 4 + j;
#pragma unroll
            for (int c4 = 0; c4 < 4; c4++) {
                float4 w = sW[k * 16 + cg * 4 + c4];
                acc[c4 * 4 + 0] = fmaf(xs, w.x, acc[c4 * 4 + 0]);
                acc[c4 * 4 + 1] = fmaf(xs, w.y, acc[c4 * 4 + 1]);
                acc[c4 * 4 + 2] = fmaf(xs, w.z, acc[c4 * 4 + 2]);
                acc[c4 * 4 + 3] = fmaf(xs, w.w, acc[c4 * 4 + 3]);
            }
        }
    }

    float s = g_inv[row], sn = s * s;
    float4* h1r = (float4*)(g_h1 + (size_t)row * FH);
    float4* a1r = (float4*)(g_a1 + (size_t)row * FH);
#pragma unroll
    for (int c4 = 0; c4 < 4; c4++) {
        float4 hv = make_float4(acc[c4 * 4 + 0], acc[c4 * 4 + 1],
                                acc[c4 * 4 + 2], acc[c4 * 4 + 3]);
        h1r[cg * 4 + c4] = hv;
        a1r[cg * 4 + c4] = make_float4(hv.x * sn, hv.y * sn, hv.z * sn, hv.w * sn);
    }
}

// scatter edges: a1[dst] += h1[src] * inv[src]*inv[dst]; 16 threads/edge, float4 each
__global__ void __launch_bounds__(256) k_scatter1(const void* ei) {
    long long t = (long long)blockIdx.x * 256 + threadIdx.x;
    int e = (int)(t >> 4);
    if (e >= N_EDGES) return;
    int q = (int)(t & 15);
    int s = load_idx(ei, 0, e);
    int d = load_idx(ei, 1, e);
    float w = g_inv[s] * g_inv[d];
    float4 v = ((const float4*)g_h1)[(size_t)s * 16 + q];
    v.x *= w; v.y *= w; v.z *= w; v.w *= w;
    red_add_f32x4(g_a1 + (size_t)d * FH + q * 4, v);
}

__global__ void k_relu_drop(const float* __restrict__ b1) {
    int i = blockIdx.x * 256 + threadIdx.x;
    if (i >= N_NODES * FH) return;
    float v = g_a1[i] + __ldg(&b1[i & (FH - 1)]);
    v = fmaxf(v, 0.0f);
    g_a1[i] = keep_mask((uint32_t)i) ? v * 2.0f : 0.0f;   // /keep, keep=0.5
}

// h2 = a1 @ W2 ; out = h2*inv^2 + b2 (self-loop + bias init of d_out)
__global__ void __launch_bounds__(128) k_gemm2(const float* __restrict__ W2,
                                               const float* __restrict__ b2,
                                               float* __restrict__ out) {
    __shared__ float4 sW[FH * 10];   // 64 x 40 floats
    __shared__ float  sb[FOUT];
    for (int idx = threadIdx.x; idx < FH * 10; idx += 128)
        sW[idx] = ((const float4*)W2)[idx];
    if (threadIdx.x < FOUT) sb[threadIdx.x] = b2[threadIdx.x];
    __syncthreads();

    int row = blockIdx.x * 128 + threadIdx.x;
    if (row >= N_NODES) return;

    const float4* ar = (const float4*)(g_a1 + (size_t)row * FH);
    float acc[FOUT];
#pragma unroll
    for (int c = 0; c < FOUT; c++) acc[c] = 0.0f;

#pragma unroll 1
    for (int k4 = 0; k4 < 16; k4++) {
        float4 av = ar[k4];
#pragma unroll
        for (int j = 0; j < 4; j++) {
            float a = (j == 0) ? av.x : (j == 1) ? av.y : (j == 2) ? av.z : av.w;
            int k = k4 * 4 + j;
#pragma unroll
            for (int c4 = 0; c4 < 10; c4++) {
                float4 w = sW[k * 10 + c4];
                acc[c4 * 4 + 0] = fmaf(a, w.x, acc[c4 * 4 + 0]);
                acc[c4 * 4 + 1] = fmaf(a, w.y, acc[c4 * 4 + 1]);
                acc[c4 * 4 + 2] = fmaf(a, w.z, acc[c4 * 4 + 2]);
                acc[c4 * 4 + 3] = fmaf(a, w.w, acc[c4 * 4 + 3]);
            }
        }
    }

    float s = g_inv[row], sn = s * s;
    float4* outr = (float4*)(out + (size_t)row * FOUT);
    float4* h2r  = (float4*)(g_h2 + (size_t)row * FOUT);
#pragma unroll
    for (int c4 = 0; c4 < 10; c4++) {
        float4 hv = make_float4(acc[c4 * 4 + 0], acc[c4 * 4 + 1],
                                acc[c4 * 4 + 2], acc[c4 * 4 + 3]);
        h2r[c4] = hv;
        outr[c4] = make_float4(hv.x * sn + sb[c4 * 4 + 0],
                               hv.y * sn + sb[c4 * 4 + 1],
                               hv.z * sn + sb[c4 * 4 + 2],
                               hv.w * sn + sb[c4 * 4 + 3]);
    }
}

__global__ void __launch_bounds__(256) k_scatter2(const void* ei, float* __restrict__ out) {
    long long t = (long long)blockIdx.x * 256 + threadIdx.x;
    int e = (int)(t >> 4);
    if (e >= N_EDGES) return;
    int q = (int)(t & 15);
    if (q >= 10) return;
    int s = load_idx(ei, 0, e);
    int d = load_idx(ei, 1, e);
    float w = g_inv[s] * g_inv[d];
    float4 v = ((const float4*)g_h2)[(size_t)s * 10 + q];
    v.x *= w; v.y *= w; v.z *= w; v.w *= w;
    red_add_f32x4(out + (size_t)d * FOUT + q * 4, v);
}

// ---------------- launch ----------------
extern "C" void kernel_launch(void* const* d_in, const int* in_sizes, int n_in,
                              void* d_out, int out_size) {
    const float* x  = (const float*)d_in[0];
    const void*  ei = d_in[1];
    const float* W1 = (const float*)d_in[2];
    const float* b1 = (const float*)d_in[3];
    const float* W2 = (const float*)d_in[4];
    const float* b2 = (const float*)d_in[5];
    float* out = (float*)d_out;

    k_detect<<<1, 32>>>((const long long*)ei);
    k_zero_deg<<<(N_NODES + 255) / 256, 256>>>();
    k_deg<<<(N_EDGES + 255) / 256, 256>>>(ei);
    k_inv<<<(N_NODES + 255) / 256, 256>>>();
    k_gemm1<<<(N_NODES + 63) / 64, 256>>>(x, W1);
    k_scatter1<<<(N_EDGES * 16 + 255) / 256, 256>>>(ei);
    k_relu_drop<<<(N_NODES * FH + 255) / 256, 256>>>(b1);
    k_gemm2<<<(N_NODES + 127) / 128, 128>>>(W2, b2, out);
    k_scatter2<<<(N_EDGES * 16 + 255) / 256, 256>>>(ei, out);
}

// round 3
// speedup vs baseline: 1.0896x; 1.0896x over previous
#include <cuda_runtime.h>
#include <cstdint>

#define N_NODES 100000
#define N_EDGES 1600000
#define FIN 128
#define FH 64
#define FOUT 40

// ---------------- scratch (device globals; no allocs allowed) ----------------
__device__ __align__(16) float g_h1p[N_NODES * FH];   // (x @ W1) * inv[row]
__device__ __align__(16) float g_a1[N_NODES * FH];    // aggregated (pre-activation)
__device__ __align__(16) float g_h2p[N_NODES * FOUT]; // (a1' @ W2) * inv[row]
__device__ int   g_deg[N_NODES];
__device__ float g_inv[N_NODES];
__device__ int   g_is64;

// ---------------- helpers ----------------
__device__ __forceinline__ void red_add_f32x4(float* p, float4 v) {
    asm volatile("red.global.add.v4.f32 [%0], {%1,%2,%3,%4};"
                 :: "l"(p), "f"(v.x), "f"(v.y), "f"(v.z), "f"(v.w) : "memory");
}

__device__ __forceinline__ int load_idx(const void* ei, int half, int e) {
    if (g_is64) return (int)((const long long*)ei)[(size_t)half * N_EDGES + e];
    return ((const int*)ei)[(size_t)half * N_EDGES + e];
}

// Threefry-2x32, 20 rounds (JAX rotation schedule)
__device__ __forceinline__ uint2 threefry2x32(uint32_t k0, uint32_t k1,
                                              uint32_t x0, uint32_t x1) {
    uint32_t ks2 = 0x1BD11BDAu ^ k0 ^ k1;
    x0 += k0; x1 += k1;
#define TF_R(r) { x0 += x1; x1 = __funnelshift_l(x1, x1, r); x1 ^= x0; }
    TF_R(13) TF_R(15) TF_R(26) TF_R(6)
    x0 += k1;  x1 += ks2 + 1u;
    TF_R(17) TF_R(29) TF_R(16) TF_R(24)
    x0 += ks2; x1 += k0 + 2u;
    TF_R(13) TF_R(15) TF_R(26) TF_R(6)
    x0 += k0;  x1 += k1 + 3u;
    TF_R(17) TF_R(29) TF_R(16) TF_R(24)
    x0 += k1;  x1 += ks2 + 4u;
    TF_R(13) TF_R(15) TF_R(26) TF_R(6)
    x0 += ks2; x1 += k0 + 5u;
#undef TF_R
    return make_uint2(x0, x1);
}

// JAX partitionable threefry: key(42) = (0,42), counter = flat index i.
__device__ __forceinline__ bool keep_mask(uint32_t i) {
    uint2 o = threefry2x32(0u, 42u, 0u, i);
    uint32_t bits = o.x ^ o.y;
    float u = __uint_as_float((bits >> 9) | 0x3f800000u) - 1.0f;
    return u < 0.5f;
}

// ---------------- kernels ----------------
// zero deg everywhere; block 0 also detects the edge-index element width
__global__ void k_init(const long long* ei) {
    __shared__ int s_ok;
    int i = blockIdx.x * 256 + threadIdx.x;
    if (i < N_NODES) g_deg[i] = 0;
    if (blockIdx.x == 0) {
        if (threadIdx.x == 0) s_ok = 1;
        __syncthreads();
        if (threadIdx.x < 128) {   // first 1KB: safe to read as either dtype
            long long v = ei[threadIdx.x];
            if (v < 0 || v >= N_NODES) atomicAnd(&s_ok, 0);
        }
        __syncthreads();
        if (threadIdx.x == 0) g_is64 = s_ok;
    }
}

__global__ void k_deg(const void* ei) {
    int e = blockIdx.x * 256 + threadIdx.x;
    if (e >= N_EDGES) return;
    atomicAdd(&g_deg[load_idx(ei, 1, e)], 1);
}

__global__ void k_inv() {
    int i = blockIdx.x * 256 + threadIdx.x;
    if (i < N_NODES) g_inv[i] = rsqrtf((float)g_deg[i] + 1.0f);
}

// h1p = (x @ W1) * inv ; a1 = h1p * inv  (self-loop init)
// block: 256 threads = 64 rows x 4 col-groups of 16 cols
__global__ void __launch_bounds__(256) k_gemm1(const float* __restrict__ x,
                                               const float* __restrict__ W1) {
    __shared__ float4 sW[FIN * 16];   // 128 x 64 floats = 32KB
    for (int idx = threadIdx.x; idx < FIN * 16; idx += 256)
        sW[idx] = ((const float4*)W1)[idx];
    __syncthreads();

    int row = blockIdx.x * 64 + (threadIdx.x >> 2);
    int cg  = threadIdx.x & 3;
    if (row >= N_NODES) return;

    const float4* xr = (const float4*)(x + (size_t)row * FIN);
    float acc[16];
#pragma unroll
    for (int i = 0; i < 16; i++) acc[i] = 0.0f;

#pragma unroll 4
    for (int k4 = 0; k4 < 32; k4++) {
        float4 xv = xr[k4];
#pragma unroll
        for (int j = 0; j < 4; j++) {
            float xs = (j == 0) ? xv.x : (j == 1) ? xv.y : (j == 2) ? xv.z : xv.w;
            int k = k4 * 4 + j;
#pragma unroll
            for (int c4 = 0; c4 < 4; c4++) {
                float4 w = sW[k * 16 + cg * 4 + c4];
                acc[c4 * 4 + 0] = fmaf(xs, w.x, acc[c4 * 4 + 0]);
                acc[c4 * 4 + 1] = fmaf(xs, w.y, acc[c4 * 4 + 1]);
                acc[c4 * 4 + 2] = fmaf(xs, w.z, acc[c4 * 4 + 2]);
                acc[c4 * 4 + 3] = fmaf(xs, w.w, acc[c4 * 4 + 3]);
            }
        }
    }

    float s = g_inv[row];
    float4* hr = (float4*)(g_h1p + (size_t)row * FH);
    float4* ar = (float4*)(g_a1  + (size_t)row * FH);
#pragma unroll
    for (int c4 = 0; c4 < 4; c4++) {
        float4 hv = make_float4(acc[c4 * 4 + 0] * s, acc[c4 * 4 + 1] * s,
                                acc[c4 * 4 + 2] * s, acc[c4 * 4 + 3] * s);
        hr[cg * 4 + c4] = hv;
        ar[cg * 4 + c4] = make_float4(hv.x * s, hv.y * s, hv.z * s, hv.w * s);
    }
}

// a1[dst] += h1p[src] * inv[dst]; 16 threads/edge, float4 payload each
__global__ void __launch_bounds__(256) k_scatter1(const void* ei) {
    long long t = (long long)blockIdx.x * 256 + threadIdx.x;
    int e = (int)(t >> 4);
    if (e >= N_EDGES) return;
    int q = (int)(t & 15);
    int s = load_idx(ei, 0, e);
    int d = load_idx(ei, 1, e);
    float w = g_inv[d];
    float4 v = ((const float4*)g_h1p)[(size_t)s * 16 + q];
    v.x *= w; v.y *= w; v.z *= w; v.w *= w;
    red_add_f32x4(g_a1 + (size_t)d * FH + q * 4, v);
}

// fused: a1' = dropout(relu(a1 + b1)) ; h2p = (a1' @ W2)*inv ; out init = h2p*inv + b2
__global__ void __launch_bounds__(128) k_gemm2(const float* __restrict__ b1,
                                               const float* __restrict__ W2,
                                               const float* __restrict__ b2,
                                               float* __restrict__ out) {
    __shared__ float4 sW[FH * 10];   // 64 x 40 floats
    __shared__ float  sb1[FH];
    __shared__ float  sb2[FOUT];
    for (int idx = threadIdx.x; idx < FH * 10; idx += 128)
        sW[idx] = ((const float4*)W2)[idx];
    if (threadIdx.x < FH)  sb1[threadIdx.x] = b1[threadIdx.x];
    if (threadIdx.x < FOUT) sb2[threadIdx.x] = b2[threadIdx.x];
    __syncthreads();

    int row = blockIdx.x * 128 + threadIdx.x;
    if (row >= N_NODES) return;

    const float4* ar = (const float4*)(g_a1 + (size_t)row * FH);
    uint32_t ibase = (uint32_t)row * FH;
    float acc[FOUT];
#pragma unroll
    for (int c = 0; c < FOUT; c++) acc[c] = 0.0f;

#pragma unroll 2
    for (int k4 = 0; k4 < 16; k4++) {
        float4 av = ar[k4];
        float vals[4];
#pragma unroll
        for (int j = 0; j < 4; j++) {
            int k = k4 * 4 + j;
            float a = (j == 0) ? av.x : (j == 1) ? av.y : (j == 2) ? av.z : av.w;
            float v = fmaxf(a + sb1[k], 0.0f);
            vals[j] = keep_mask(ibase + k) ? v * 2.0f : 0.0f;   // keep=0.5 -> /0.5
        }
#pragma unroll
        for (int j = 0; j < 4; j++) {
            float a = vals[j];
            int k = k4 * 4 + j;
#pragma unroll
            for (int c4 = 0; c4 < 10; c4++) {
                float4 w = sW[k * 10 + c4];
                acc[c4 * 4 + 0] = fmaf(a, w.x, acc[c4 * 4 + 0]);
                acc[c4 * 4 + 1] = fmaf(a, w.y, acc[c4 * 4 + 1]);
                acc[c4 * 4 + 2] = fmaf(a, w.z, acc[c4 * 4 + 2]);
                acc[c4 * 4 + 3] = fmaf(a, w.w, acc[c4 * 4 + 3]);
            }
        }
    }

    float s = g_inv[row];
    float4* outr = (float4*)(out + (size_t)row * FOUT);
    float4* h2r  = (float4*)(g_h2p + (size_t)row * FOUT);
#pragma unroll
    for (int c4 = 0; c4 < 10; c4++) {
        float4 hv = make_float4(acc[c4 * 4 + 0] * s, acc[c4 * 4 + 1] * s,
                                acc[c4 * 4 + 2] * s, acc[c4 * 4 + 3] * s);
        h2r[c4] = hv;
        outr[c4] = make_float4(hv.x * s + sb2[c4 * 4 + 0],
                               hv.y * s + sb2[c4 * 4 + 1],
                               hv.z * s + sb2[c4 * 4 + 2],
                               hv.w * s + sb2[c4 * 4 + 3]);
    }
}

// out[dst] += h2p[src] * inv[dst]; dense 10 threads/edge
__global__ void __launch_bounds__(320) k_scatter2(const void* ei, float* __restrict__ out) {
    long long t = (long long)blockIdx.x * 320 + threadIdx.x;
    int e = (int)(t / 10);
    if (e >= N_EDGES) return;
    int q = (int)(t - (long long)e * 10);
    int s = load_idx(ei, 0, e);
    int d = load_idx(ei, 1, e);
    float w = g_inv[d];
    float4 v = ((const float4*)g_h2p)[(size_t)s * 10 + q];
    v.x *= w; v.y *= w; v.z *= w; v.w *= w;
    red_add_f32x4(out + (size_t)d * FOUT + q * 4, v);
}

// ---------------- launch ----------------
extern "C" void kernel_launch(void* const* d_in, const int* in_sizes, int n_in,
                              void* d_out, int out_size) {
    const float* x  = (const float*)d_in[0];
    const void*  ei = d_in[1];
    const float* W1 = (const float*)d_in[2];
    const float* b1 = (const float*)d_in[3];
    const float* W2 = (const float*)d_in[4];
    const float* b2 = (const float*)d_in[5];
    float* out = (float*)d_out;

    k_init<<<(N_NODES + 255) / 256, 256>>>((const long long*)ei);
    k_deg<<<(N_EDGES + 255) / 256, 256>>>(ei);
    k_inv<<<(N_NODES + 255) / 256, 256>>>();
    k_gemm1<<<(N_NODES + 63) / 64, 256>>>(x, W1);
    k_scatter1<<<(int)(((long long)N_EDGES * 16 + 255) / 256), 256>>>(ei);
    k_gemm2<<<(N_NODES + 127) / 128, 128>>>(b1, W2, b2, out);
    k_scatter2<<<(int)(((long long)N_EDGES * 10 + 319) / 320), 320>>>(ei, out);
}

// round 6
// speedup vs baseline: 1.5236x; 1.3984x over previous
#include <cuda_runtime.h>
#include <cstdint>

#define N_NODES 100000
#define N_EDGES 1600000
#define FIN 128
#define FH 64
#define FOUT 40

// ---------------- scratch (device globals; no allocs allowed) ----------------
__device__ __align__(16) float g_h1p[N_NODES * FH];   // (x @ W1) * inv[row]
__device__ __align__(16) float g_a1[N_NODES * FH];    // aggregated (pre-activation)
__device__ __align__(16) float g_h2p[N_NODES * FOUT]; // (a1' @ W2) * inv[row]
__device__ int   g_deg[N_NODES];
__device__ float g_inv[N_NODES];
__device__ int   g_is64;

// ---------------- helpers ----------------
__device__ __forceinline__ void red_add_f32x4(float* p, float4 v) {
    asm volatile("red.global.add.v4.f32 [%0], {%1,%2,%3,%4};"
                 :: "l"(p), "f"(v.x), "f"(v.y), "f"(v.z), "f"(v.w) : "memory");
}

__device__ __forceinline__ int load_idx(const void* ei, int half, int e) {
    if (g_is64) return (int)((const long long*)ei)[(size_t)half * N_EDGES + e];
    return ((const int*)ei)[(size_t)half * N_EDGES + e];
}

// Threefry-2x32, 20 rounds (JAX rotation schedule) — verified bit-exact vs ref
__device__ __forceinline__ uint2 threefry2x32(uint32_t k0, uint32_t k1,
                                              uint32_t x0, uint32_t x1) {
    uint32_t ks2 = 0x1BD11BDAu ^ k0 ^ k1;
    x0 += k0; x1 += k1;
#define TF_R(r) { x0 += x1; x1 = __funnelshift_l(x1, x1, r); x1 ^= x0; }
    TF_R(13) TF_R(15) TF_R(26) TF_R(6)
    x0 += k1;  x1 += ks2 + 1u;
    TF_R(17) TF_R(29) TF_R(16) TF_R(24)
    x0 += ks2; x1 += k0 + 2u;
    TF_R(13) TF_R(15) TF_R(26) TF_R(6)
    x0 += k0;  x1 += k1 + 3u;
    TF_R(17) TF_R(29) TF_R(16) TF_R(24)
    x0 += k1;  x1 += ks2 + 4u;
    TF_R(13) TF_R(15) TF_R(26) TF_R(6)
    x0 += ks2; x1 += k0 + 5u;
#undef TF_R
    return make_uint2(x0, x1);
}

__device__ __forceinline__ bool keep_mask(uint32_t i) {
    uint2 o = threefry2x32(0u, 42u, 0u, i);
    uint32_t bits = o.x ^ o.y;
    float u = __uint_as_float((bits >> 9) | 0x3f800000u) - 1.0f;
    return u < 0.5f;
}

// ---------------- small kernels ----------------
__global__ void k_init(const long long* ei) {
    __shared__ int s_ok;
    int i = blockIdx.x * 256 + threadIdx.x;
    if (i < N_NODES) g_deg[i] = 0;
    if (blockIdx.x == 0) {
        if (threadIdx.x == 0) s_ok = 1;
        __syncthreads();
        if (threadIdx.x < 128) {
            long long v = ei[threadIdx.x];
            if (v < 0 || v >= N_NODES) atomicAnd(&s_ok, 0);
        }
        __syncthreads();
        if (threadIdx.x == 0) g_is64 = s_ok;
    }
}

__global__ void k_deg(const void* ei) {
    int e = blockIdx.x * 256 + threadIdx.x;
    if (e >= N_EDGES) return;
    atomicAdd(&g_deg[load_idx(ei, 1, e)], 1);
}

__global__ void k_inv() {
    int i = blockIdx.x * 256 + threadIdx.x;
    if (i < N_NODES) g_inv[i] = rsqrtf((float)g_deg[i] + 1.0f);
}

// ---------------- gemm1: register-blocked 128x64, thread tile 8x8 ----------------
// h1p = (x @ W1) * inv ; a1 = h1p * inv  (self-loop init)
// smem: sW 32KB + sX 8.5KB = 40.5KB < 48KB static limit
#define KC 16
#define XPAD 17
__global__ void __launch_bounds__(128) k_gemm1(const float* __restrict__ x,
                                               const float* __restrict__ W1) {
    __shared__ float sW[FIN * FH];        // 32KB, [k][col]
    __shared__ float sX[128 * XPAD];      // 8.5KB, [row][k] chunk of 16, pad 17

    int tid = threadIdx.x;
    // load full W1 (8192 floats = 2048 float4)
    for (int idx = tid; idx < FIN * FH / 4; idx += 128)
        ((float4*)sW)[idx] = ((const float4*)W1)[idx];

    int row0 = blockIdx.x * 128;
    int cg = tid & 7;        // col group: cols cg*8 .. cg*8+7
    int rg = tid >> 3;       // row group: rows rg*8 .. rg*8+7 (rg 0..15)

    float acc[64];
#pragma unroll
    for (int i = 0; i < 64; i++) acc[i] = 0.0f;

    int k4 = tid & 3;        // staging: float4 index within 16-k chunk
    int rr = tid >> 2;       // staging: row stride-32 base (0..31)

#pragma unroll 1
    for (int kc = 0; kc < FIN / KC; kc++) {
        __syncthreads();
        // stage x[row0..row0+127][kc*16..+16) into sX[row][k]
#pragma unroll
        for (int p = 0; p < 4; p++) {
            int r = rr + p * 32;
            int grow = row0 + r;
            float4 v = make_float4(0.f, 0.f, 0.f, 0.f);
            if (grow < N_NODES)
                v = ((const float4*)(x + (size_t)grow * FIN + kc * KC))[k4];
            float* dst = sX + r * XPAD + k4 * 4;
            dst[0] = v.x; dst[1] = v.y; dst[2] = v.z; dst[3] = v.w;
        }
        __syncthreads();

#pragma unroll
        for (int k = 0; k < KC; k++) {
            float xv[8];
#pragma unroll
            for (int i = 0; i < 8; i++) xv[i] = sX[(rg * 8 + i) * XPAD + k];
            const float4* wp = (const float4*)(sW + (kc * KC + k) * FH + cg * 8);
            float4 wa = wp[0], wb = wp[1];
#pragma unroll
            for (int i = 0; i < 8; i++) {
                acc[i * 8 + 0] = fmaf(xv[i], wa.x, acc[i * 8 + 0]);
                acc[i * 8 + 1] = fmaf(xv[i], wa.y, acc[i * 8 + 1]);
                acc[i * 8 + 2] = fmaf(xv[i], wa.z, acc[i * 8 + 2]);
                acc[i * 8 + 3] = fmaf(xv[i], wa.w, acc[i * 8 + 3]);
                acc[i * 8 + 4] = fmaf(xv[i], wb.x, acc[i * 8 + 4]);
                acc[i * 8 + 5] = fmaf(xv[i], wb.y, acc[i * 8 + 5]);
                acc[i * 8 + 6] = fmaf(xv[i], wb.z, acc[i * 8 + 6]);
                acc[i * 8 + 7] = fmaf(xv[i], wb.w, acc[i * 8 + 7]);
            }
        }
    }

    // epilogue: h1p = acc*s ; a1 = acc*s*s
#pragma unroll
    for (int i = 0; i < 8; i++) {
        int grow = row0 + rg * 8 + i;
        if (grow >= N_NODES) break;
        float s = g_inv[grow];
        float4* hr = (float4*)(g_h1p + (size_t)grow * FH + cg * 8);
        float4* ar = (float4*)(g_a1  + (size_t)grow * FH + cg * 8);
#pragma unroll
        for (int h = 0; h < 2; h++) {
            float4 hv = make_float4(acc[i * 8 + h * 4 + 0] * s, acc[i * 8 + h * 4 + 1] * s,
                                    acc[i * 8 + h * 4 + 2] * s, acc[i * 8 + h * 4 + 3] * s);
            hr[h] = hv;
            ar[h] = make_float4(hv.x * s, hv.y * s, hv.z * s, hv.w * s);
        }
    }
}

// a1[dst] += h1p[src] * inv[dst]; 16 threads/edge, float4 payload
__global__ void __launch_bounds__(256) k_scatter1(const void* ei) {
    long long t = (long long)blockIdx.x * 256 + threadIdx.x;
    int e = (int)(t >> 4);
    if (e >= N_EDGES) return;
    int q = (int)(t & 15);
    int s = load_idx(ei, 0, e);
    int d = load_idx(ei, 1, e);
    float w = g_inv[d];
    float4 v = ((const float4*)g_h1p)[(size_t)s * 16 + q];
    v.x *= w; v.y *= w; v.z *= w; v.w *= w;
    red_add_f32x4(g_a1 + (size_t)d * FH + q * 4, v);
}

// ---------------- gemm2: fused transform + register-blocked 128x40, tile 8x5 ----
#define APAD 65
__global__ void __launch_bounds__(128) k_gemm2(const float* __restrict__ b1,
                                               const float* __restrict__ W2,
                                               const float* __restrict__ b2,
                                               float* __restrict__ out) {
    __shared__ float sW[FH * FOUT];       // 10.2KB, [k][col]
    __shared__ float sA[128 * APAD];      // 33.3KB, [row][k], pad 65
    __shared__ float sb1[FH];
    __shared__ float sb2[FOUT];

    int tid = threadIdx.x;
    for (int idx = tid; idx < FH * FOUT / 4; idx += 128)
        ((float4*)sW)[idx] = ((const float4*)W2)[idx];
    if (tid < FH)   sb1[tid] = b1[tid];
    if (tid < FOUT) sb2[tid] = b2[tid];
    __syncthreads();

    int row0 = blockIdx.x * 128;

    // stage a1 with fused bias+relu+dropout: layout (k4 = tid&15, row base tid>>4)
    {
        int k4 = tid & 15;
        int rr = tid >> 4;   // 0..7
#pragma unroll
        for (int p = 0; p < 16; p++) {
            int r = rr + p * 8;
            int grow = row0 + r;
            float4 v = make_float4(0.f, 0.f, 0.f, 0.f);
            if (grow < N_NODES) {
                v = ((const float4*)(g_a1 + (size_t)grow * FH))[k4];
                uint32_t ib = (uint32_t)grow * FH + k4 * 4;
                float t0 = fmaxf(v.x + sb1[k4 * 4 + 0], 0.0f);
                float t1 = fmaxf(v.y + sb1[k4 * 4 + 1], 0.0f);
                float t2 = fmaxf(v.z + sb1[k4 * 4 + 2], 0.0f);
                float t3 = fmaxf(v.w + sb1[k4 * 4 + 3], 0.0f);
                v.x = keep_mask(ib + 0) ? t0 * 2.0f : 0.0f;
                v.y = keep_mask(ib + 1) ? t1 * 2.0f : 0.0f;
                v.z = keep_mask(ib + 2) ? t2 * 2.0f : 0.0f;
                v.w = keep_mask(ib + 3) ? t3 * 2.0f : 0.0f;
            }
            float* dst = sA + r * APAD + k4 * 4;
            dst[0] = v.x; dst[1] = v.y; dst[2] = v.z; dst[3] = v.w;
        }
    }
    __syncthreads();

    int cg = tid & 7;        // col group: cols cg*5 .. cg*5+4
    int rg = tid >> 3;       // row group: rows rg*8 .. rg*8+7

    float acc[40];
#pragma unroll
    for (int c = 0; c < 40; c++) acc[c] = 0.0f;

#pragma unroll 4
    for (int k = 0; k < FH; k++) {
        float xv[8];
#pragma unroll
        for (int i = 0; i < 8; i++) xv[i] = sA[(rg * 8 + i) * APAD + k];
        float wv[5];
#pragma unroll
        for (int c = 0; c < 5; c++) wv[c] = sW[k * FOUT + cg * 5 + c];
#pragma unroll
        for (int i = 0; i < 8; i++)
#pragma unroll
            for (int c = 0; c < 5; c++)
                acc[i * 5 + c] = fmaf(xv[i], wv[c], acc[i * 5 + c]);
    }

    // epilogue: h2p = acc*s ; out = acc*s*s + b2
#pragma unroll
    for (int i = 0; i < 8; i++) {
        int grow = row0 + rg * 8 + i;
        if (grow >= N_NODES) break;
        float s = g_inv[grow];
        float* hr = g_h2p + (size_t)grow * FOUT + cg * 5;
        float* orow = out + (size_t)grow * FOUT + cg * 5;
#pragma unroll
        for (int c = 0; c < 5; c++) {
            float hv = acc[i * 5 + c] * s;
            hr[c] = hv;
            orow[c] = hv * s + sb2[cg * 5 + c];
        }
    }
}

// out[dst] += h2p[src] * inv[dst]; dense 10 threads/edge
__global__ void __launch_bounds__(320) k_scatter2(const void* ei, float* __restrict__ out) {
    long long t = (long long)blockIdx.x * 320 + threadIdx.x;
    int e = (int)(t / 10);
    if (e >= N_EDGES) return;
    int q = (int)(t - (long long)e * 10);
    int s = load_idx(ei, 0, e);
    int d = load_idx(ei, 1, e);
    float w = g_inv[d];
    float4 v = ((const float4*)g_h2p)[(size_t)s * 10 + q];
    v.x *= w; v.y *= w; v.z *= w; v.w *= w;
    red_add_f32x4(out + (size_t)d * FOUT + q * 4, v);
}

// ---------------- launch ----------------
extern "C" void kernel_launch(void* const* d_in, const int* in_sizes, int n_in,
                              void* d_out, int out_size) {
    const float* x  = (const float*)d_in[0];
    const void*  ei = d_in[1];
    const float* W1 = (const float*)d_in[2];
    const float* b1 = (const float*)d_in[3];
    const float* W2 = (const float*)d_in[4];
    const float* b2 = (const float*)d_in[5];
    float* out = (float*)d_out;

    k_init<<<(N_NODES + 255) / 256, 256>>>((const long long*)ei);
    k_deg<<<(N_EDGES + 255) / 256, 256>>>(ei);
    k_inv<<<(N_NODES + 255) / 256, 256>>>();
    k_gemm1<<<(N_NODES + 127) / 128, 128>>>(x, W1);
    k_scatter1<<<(int)(((long long)N_EDGES * 16 + 255) / 256), 256>>>(ei);
    k_gemm2<<<(N_NODES + 127) / 128, 128>>>(b1, W2, b2, out);
    k_scatter2<<<(int)(((long long)N_EDGES * 10 + 319) / 320), 320>>>(ei, out);
}

// round 9
// speedup vs baseline: 2.3679x; 1.5541x over previous
#include <cuda_runtime.h>
#include <cstdint>

#define N_NODES 100000
#define N_EDGES 1600000
#define FIN 128
#define FH 64
#define FOUT 40
#define MAXD 64    // ELL cap; in-deg ~ Poisson(16), P(any node >= 64) < 1e-15

// ---------------- scratch (device globals; no allocs allowed) ----------------
__device__ __align__(16) float g_h1p[N_NODES * FH];   // (x @ W1) * inv[row]
__device__ __align__(16) float g_a1[N_NODES * FH];    // aggregated (pre-activation)
__device__ __align__(16) float g_h2p[N_NODES * FOUT]; // (a1' @ W2) * inv[row]
__device__ int   g_srcs[(size_t)N_NODES * MAXD];      // ELL in-edge source lists
__device__ int   g_deg[N_NODES];
__device__ float g_inv[N_NODES];
__device__ int   g_is64;

// ---------------- helpers ----------------
__device__ __forceinline__ int load_idx(const void* ei, int half, int e) {
    if (g_is64) return (int)((const long long*)ei)[(size_t)half * N_EDGES + e];
    return ((const int*)ei)[(size_t)half * N_EDGES + e];
}

// Threefry-2x32, 20 rounds (JAX rotation schedule) — verified bit-exact vs ref
__device__ __forceinline__ uint2 threefry2x32(uint32_t k0, uint32_t k1,
                                              uint32_t x0, uint32_t x1) {
    uint32_t ks2 = 0x1BD11BDAu ^ k0 ^ k1;
    x0 += k0; x1 += k1;
#define TF_R(r) { x0 += x1; x1 = __funnelshift_l(x1, x1, r); x1 ^= x0; }
    TF_R(13) TF_R(15) TF_R(26) TF_R(6)
    x0 += k1;  x1 += ks2 + 1u;
    TF_R(17) TF_R(29) TF_R(16) TF_R(24)
    x0 += ks2; x1 += k0 + 2u;
    TF_R(13) TF_R(15) TF_R(26) TF_R(6)
    x0 += k0;  x1 += k1 + 3u;
    TF_R(17) TF_R(29) TF_R(16) TF_R(24)
    x0 += k1;  x1 += ks2 + 4u;
    TF_R(13) TF_R(15) TF_R(26) TF_R(6)
    x0 += ks2; x1 += k0 + 5u;
#undef TF_R
    return make_uint2(x0, x1);
}

__device__ __forceinline__ bool keep_mask(uint32_t i) {
    uint2 o = threefry2x32(0u, 42u, 0u, i);
    uint32_t bits = o.x ^ o.y;
    float u = __uint_as_float((bits >> 9) | 0x3f800000u) - 1.0f;
    return u < 0.5f;
}

// ---------------- small kernels ----------------
__global__ void k_init(const long long* ei) {
    __shared__ int s_ok;
    int i = blockIdx.x * 256 + threadIdx.x;
    if (i < N_NODES) g_deg[i] = 0;
    if (blockIdx.x == 0) {
        if (threadIdx.x == 0) s_ok = 1;
        __syncthreads();
        if (threadIdx.x < 128) {
            long long v = ei[threadIdx.x];
            if (v < 0 || v >= N_NODES) atomicAnd(&s_ok, 0);
        }
        __syncthreads();
        if (threadIdx.x == 0) g_is64 = s_ok;
    }
}

// count in-degree AND bucket edges into ELL rows in one pass
__global__ void k_bucket(const void* ei) {
    int e = blockIdx.x * 256 + threadIdx.x;
    if (e >= N_EDGES) return;
    int s = load_idx(ei, 0, e);
    int d = load_idx(ei, 1, e);
    int pos = atomicAdd(&g_deg[d], 1);
    if (pos < MAXD) g_srcs[(size_t)d * MAXD + pos] = s;
}

__global__ void k_inv() {
    int i = blockIdx.x * 256 + threadIdx.x;
    if (i < N_NODES) g_inv[i] = rsqrtf((float)g_deg[i] + 1.0f);
}

// ---------------- gemm1: register-blocked 128x64, thread tile 8x8 ----------------
// h1p = (x @ W1) * inv[row]
#define KC 16
#define XPAD 17
__global__ void __launch_bounds__(128) k_gemm1(const float* __restrict__ x,
                                               const float* __restrict__ W1) {
    __shared__ float sW[FIN * FH];        // 32KB, [k][col]
    __shared__ float sX[128 * XPAD];      // 8.5KB, [row][k] chunk of 16, pad 17

    int tid = threadIdx.x;
    for (int idx = tid; idx < FIN * FH / 4; idx += 128)
        ((float4*)sW)[idx] = ((const float4*)W1)[idx];

    int row0 = blockIdx.x * 128;
    int cg = tid & 7;
    int rg = tid >> 3;

    float acc[64];
#pragma unroll
    for (int i = 0; i < 64; i++) acc[i] = 0.0f;

    int k4 = tid & 3;
    int rr = tid >> 2;

#pragma unroll 1
    for (int kc = 0; kc < FIN / KC; kc++) {
        __syncthreads();
#pragma unroll
        for (int p = 0; p < 4; p++) {
            int r = rr + p * 32;
            int grow = row0 + r;
            float4 v = make_float4(0.f, 0.f, 0.f, 0.f);
            if (grow < N_NODES)
                v = ((const float4*)(x + (size_t)grow * FIN + kc * KC))[k4];
            float* dst = sX + r * XPAD + k4 * 4;
            dst[0] = v.x; dst[1] = v.y; dst[2] = v.z; dst[3] = v.w;
        }
        __syncthreads();

#pragma unroll
        for (int k = 0; k < KC; k++) {
            float xv[8];
#pragma unroll
            for (int i = 0; i < 8; i++) xv[i] = sX[(rg * 8 + i) * XPAD + k];
            const float4* wp = (const float4*)(sW + (kc * KC + k) * FH + cg * 8);
            float4 wa = wp[0], wb = wp[1];
#pragma unroll
            for (int i = 0; i < 8; i++) {
                acc[i * 8 + 0] = fmaf(xv[i], wa.x, acc[i * 8 + 0]);
                acc[i * 8 + 1] = fmaf(xv[i], wa.y, acc[i * 8 + 1]);
                acc[i * 8 + 2] = fmaf(xv[i], wa.z, acc[i * 8 + 2]);
                acc[i * 8 + 3] = fmaf(xv[i], wa.w, acc[i * 8 + 3]);
                acc[i * 8 + 4] = fmaf(xv[i], wb.x, acc[i * 8 + 4]);
                acc[i * 8 + 5] = fmaf(xv[i], wb.y, acc[i * 8 + 5]);
                acc[i * 8 + 6] = fmaf(xv[i], wb.z, acc[i * 8 + 6]);
                acc[i * 8 + 7] = fmaf(xv[i], wb.w, acc[i * 8 + 7]);
            }
        }
    }

#pragma unroll
    for (int i = 0; i < 8; i++) {
        int grow = row0 + rg * 8 + i;
        if (grow >= N_NODES) break;
        float s = g_inv[grow];
        float4* hr = (float4*)(g_h1p + (size_t)grow * FH + cg * 8);
#pragma unroll
        for (int h = 0; h < 2; h++)
            hr[h] = make_float4(acc[i * 8 + h * 4 + 0] * s, acc[i * 8 + h * 4 + 1] * s,
                                acc[i * 8 + h * 4 + 2] * s, acc[i * 8 + h * 4 + 3] * s);
    }
}

// gather-aggregate layer1: a1[d] = inv[d] * (sum_in h1p[src] + h1p[d])
// 16 lanes per dst, one float4 slot each
__global__ void __launch_bounds__(256) k_agg1() {
    long long t = (long long)blockIdx.x * 256 + threadIdx.x;
    int d = (int)(t >> 4);
    if (d >= N_NODES) return;
    int q = (int)(t & 15);
    int cnt = g_deg[d];
    if (cnt > MAXD) cnt = MAXD;
    const int* sp = g_srcs + (size_t)d * MAXD;
    float4 acc = ((const float4*)g_h1p)[(size_t)d * 16 + q];   // self term
#pragma unroll 2
    for (int j = 0; j < cnt; j++) {
        int s = __ldg(&sp[j]);
        float4 v = ((const float4*)g_h1p)[(size_t)s * 16 + q];
        acc.x += v.x; acc.y += v.y; acc.z += v.z; acc.w += v.w;
    }
    float w = g_inv[d];
    ((float4*)g_a1)[(size_t)d * 16 + q] =
        make_float4(acc.x * w, acc.y * w, acc.z * w, acc.w * w);
}

// ---------------- gemm2: fused transform + register-blocked 128x40, tile 8x5 ----
#define APAD 65
__global__ void __launch_bounds__(128) k_gemm2(const float* __restrict__ b1,
                                               const float* __restrict__ W2) {
    __shared__ float sW[FH * FOUT];       // 10.2KB
    __shared__ float sA[128 * APAD];      // 33.3KB
    __shared__ float sb1[FH];

    int tid = threadIdx.x;
    for (int idx = tid; idx < FH * FOUT / 4; idx += 128)
        ((float4*)sW)[idx] = ((const float4*)W2)[idx];
    if (tid < FH) sb1[tid] = b1[tid];
    __syncthreads();

    int row0 = blockIdx.x * 128;

    // stage a1 with fused bias+relu+dropout
    {
        int k4 = tid & 15;
        int rr = tid >> 4;
#pragma unroll
        for (int p = 0; p < 16; p++) {
            int r = rr + p * 8;
            int grow = row0 + r;
            float4 v = make_float4(0.f, 0.f, 0.f, 0.f);
            if (grow < N_NODES) {
                v = ((const float4*)(g_a1 + (size_t)grow * FH))[k4];
                uint32_t ib = (uint32_t)grow * FH + k4 * 4;
                float t0 = fmaxf(v.x + sb1[k4 * 4 + 0], 0.0f);
                float t1 = fmaxf(v.y + sb1[k4 * 4 + 1], 0.0f);
                float t2 = fmaxf(v.z + sb1[k4 * 4 + 2], 0.0f);
                float t3 = fmaxf(v.w + sb1[k4 * 4 + 3], 0.0f);
                v.x = keep_mask(ib + 0) ? t0 * 2.0f : 0.0f;
                v.y = keep_mask(ib + 1) ? t1 * 2.0f : 0.0f;
                v.z = keep_mask(ib + 2) ? t2 * 2.0f : 0.0f;
                v.w = keep_mask(ib + 3) ? t3 * 2.0f : 0.0f;
            }
            float* dst = sA + r * APAD + k4 * 4;
            dst[0] = v.x; dst[1] = v.y; dst[2] = v.z; dst[3] = v.w;
        }
    }
    __syncthreads();

    int cg = tid & 7;
    int rg = tid >> 3;

    float acc[40];
#pragma unroll
    for (int c = 0; c < 40; c++) acc[c] = 0.0f;

#pragma unroll 4
    for (int k = 0; k < FH; k++) {
        float xv[8];
#pragma unroll
        for (int i = 0; i < 8; i++) xv[i] = sA[(rg * 8 + i) * APAD + k];
        float wv[5];
#pragma unroll
        for (int c = 0; c < 5; c++) wv[c] = sW[k * FOUT + cg * 5 + c];
#pragma unroll
        for (int i = 0; i < 8; i++)
#pragma unroll
            for (int c = 0; c < 5; c++)
                acc[i * 5 + c] = fmaf(xv[i], wv[c], acc[i * 5 + c]);
    }

    // epilogue: h2p = acc * inv[row]
#pragma unroll
    for (int i = 0; i < 8; i++) {
        int grow = row0 + rg * 8 + i;
        if (grow >= N_NODES) break;
        float s = g_inv[grow];
        float* hr = g_h2p + (size_t)grow * FOUT + cg * 5;
#pragma unroll
        for (int c = 0; c < 5; c++)
            hr[c] = acc[i * 5 + c] * s;
    }
}

// gather-aggregate layer2: out[d] = inv[d]*(sum_in h2p[src] + h2p[d]) + b2
// 10 lanes per dst, one float4 slot each
__global__ void __launch_bounds__(320) k_agg2(const float* __restrict__ b2,
                                              float* __restrict__ out) {
    long long t = (long long)blockIdx.x * 320 + threadIdx.x;
    int d = (int)(t / 10);
    if (d >= N_NODES) return;
    int q = (int)(t - (long long)d * 10);
    int cnt = g_deg[d];
    if (cnt > MAXD) cnt = MAXD;
    const int* sp = g_srcs + (size_t)d * MAXD;
    float4 acc = ((const float4*)g_h2p)[(size_t)d * 10 + q];   // self term
#pragma unroll 2
    for (int j = 0; j < cnt; j++) {
        int s = __ldg(&sp[j]);
        float4 v = ((const float4*)g_h2p)[(size_t)s * 10 + q];
        acc.x += v.x; acc.y += v.y; acc.z += v.z; acc.w += v.w;
    }
    float w = g_inv[d];
    float4 bv = ((const float4*)b2)[q];
    ((float4*)out)[(size_t)d * 10 + q] =
        make_float4(acc.x * w + bv.x, acc.y * w + bv.y,
                    acc.z * w + bv.z, acc.w * w + bv.w);
}

// ---------------- launch ----------------
extern "C" void kernel_launch(void* const* d_in, const int* in_sizes, int n_in,
                              void* d_out, int out_size) {
    const float* x  = (const float*)d_in[0];
    const void*  ei = d_in[1];
    const float* W1 = (const float*)d_in[2];
    const float* b1 = (const float*)d_in[3];
    const float* W2 = (const float*)d_in[4];
    const float* b2 = (const float*)d_in[5];
    float* out = (float*)d_out;

    k_init<<<(N_NODES + 255) / 256, 256>>>((const long long*)ei);
    k_bucket<<<(N_EDGES + 255) / 256, 256>>>(ei);
    k_inv<<<(N_NODES + 255) / 256, 256>>>();
    k_gemm1<<<(N_NODES + 127) / 128, 128>>>(x, W1);
    k_agg1<<<(int)(((long long)N_NODES * 16 + 255) / 256), 256>>>();
    k_gemm2<<<(N_NODES + 127) / 128, 128>>>(b1, W2);
    k_agg2<<<(int)(((long long)N_NODES * 10 + 319) / 320), 320>>>(b2, out);
}

// round 10
// speedup vs baseline: 2.5271x; 1.0672x over previous
#include <cuda_runtime.h>
#include <cuda_fp16.h>
#include <cstdint>

#define N_NODES 100000
#define N_EDGES 1600000
#define FIN 128
#define FH 64
#define FOUT 40
#define MAXD 64    // ELL cap; in-deg ~ Poisson(16), P(any node >= 64) < 1e-15

// ---------------- scratch (device globals; no allocs allowed) ----------------
__device__ __align__(16) __half2 g_h1ph[(size_t)N_NODES * 32]; // (x@W1)*inv, fp16, 64/row
__device__ __align__(16) __half2 g_h2ph[(size_t)N_NODES * 20]; // (a1'@W2)*inv, fp16, 40/row
__device__ __align__(16) float   g_a1[N_NODES * FH];           // aggregated (fp32, exact path)
__device__ int   g_srcs[(size_t)N_NODES * MAXD];               // ELL in-edge source lists
__device__ int   g_deg[N_NODES];
__device__ float g_inv[N_NODES];
__device__ int   g_is64;

struct alignas(16) H8 { __half2 a, b, c, d; };

// ---------------- helpers ----------------
__device__ __forceinline__ int load_idx(const void* ei, int half, int e) {
    if (g_is64) return (int)((const long long*)ei)[(size_t)half * N_EDGES + e];
    return ((const int*)ei)[(size_t)half * N_EDGES + e];
}

// Threefry-2x32, 20 rounds (JAX rotation schedule) — verified bit-exact vs ref
__device__ __forceinline__ uint2 threefry2x32(uint32_t k0, uint32_t k1,
                                              uint32_t x0, uint32_t x1) {
    uint32_t ks2 = 0x1BD11BDAu ^ k0 ^ k1;
    x0 += k0; x1 += k1;
#define TF_R(r) { x0 += x1; x1 = __funnelshift_l(x1, x1, r); x1 ^= x0; }
    TF_R(13) TF_R(15) TF_R(26) TF_R(6)
    x0 += k1;  x1 += ks2 + 1u;
    TF_R(17) TF_R(29) TF_R(16) TF_R(24)
    x0 += ks2; x1 += k0 + 2u;
    TF_R(13) TF_R(15) TF_R(26) TF_R(6)
    x0 += k0;  x1 += k1 + 3u;
    TF_R(17) TF_R(29) TF_R(16) TF_R(24)
    x0 += k1;  x1 += ks2 + 4u;
    TF_R(13) TF_R(15) TF_R(26) TF_R(6)
    x0 += ks2; x1 += k0 + 5u;
#undef TF_R
    return make_uint2(x0, x1);
}

__device__ __forceinline__ bool keep_mask(uint32_t i) {
    uint2 o = threefry2x32(0u, 42u, 0u, i);
    uint32_t bits = o.x ^ o.y;
    float u = __uint_as_float((bits >> 9) | 0x3f800000u) - 1.0f;
    return u < 0.5f;
}

// ---------------- small kernels ----------------
__global__ void k_init(const long long* ei) {
    __shared__ int s_ok;
    int i = blockIdx.x * 256 + threadIdx.x;
    if (i < N_NODES) g_deg[i] = 0;
    if (blockIdx.x == 0) {
        if (threadIdx.x == 0) s_ok = 1;
        __syncthreads();
        if (threadIdx.x < 128) {
            long long v = ei[threadIdx.x];
            if (v < 0 || v >= N_NODES) atomicAnd(&s_ok, 0);
        }
        __syncthreads();
        if (threadIdx.x == 0) g_is64 = s_ok;
    }
}

__global__ void k_bucket(const void* ei) {
    int e = blockIdx.x * 256 + threadIdx.x;
    if (e >= N_EDGES) return;
    int s = load_idx(ei, 0, e);
    int d = load_idx(ei, 1, e);
    int pos = atomicAdd(&g_deg[d], 1);
    if (pos < MAXD) g_srcs[(size_t)d * MAXD + pos] = s;
}

__global__ void k_inv() {
    int i = blockIdx.x * 256 + threadIdx.x;
    if (i < N_NODES) g_inv[i] = rsqrtf((float)g_deg[i] + 1.0f);
}

// ---------------- gemm1: register-blocked 128x64, thread tile 8x8 ----------------
// h1ph = fp16( (x @ W1) * inv[row] )
#define KC 16
#define XPAD 17
__global__ void __launch_bounds__(128) k_gemm1(const float* __restrict__ x,
                                               const float* __restrict__ W1) {
    __shared__ float sW[FIN * FH];        // 32KB, [k][col]
    __shared__ float sX[128 * XPAD];      // 8.5KB, [row][k] chunk of 16, pad 17

    int tid = threadIdx.x;
    for (int idx = tid; idx < FIN * FH / 4; idx += 128)
        ((float4*)sW)[idx] = ((const float4*)W1)[idx];

    int row0 = blockIdx.x * 128;
    int cg = tid & 7;
    int rg = tid >> 3;

    float acc[64];
#pragma unroll
    for (int i = 0; i < 64; i++) acc[i] = 0.0f;

    int k4 = tid & 3;
    int rr = tid >> 2;

#pragma unroll 1
    for (int kc = 0; kc < FIN / KC; kc++) {
        __syncthreads();
#pragma unroll
        for (int p = 0; p < 4; p++) {
            int r = rr + p * 32;
            int grow = row0 + r;
            float4 v = make_float4(0.f, 0.f, 0.f, 0.f);
            if (grow < N_NODES)
                v = ((const float4*)(x + (size_t)grow * FIN + kc * KC))[k4];
            float* dst = sX + r * XPAD + k4 * 4;
            dst[0] = v.x; dst[1] = v.y; dst[2] = v.z; dst[3] = v.w;
        }
        __syncthreads();

#pragma unroll
        for (int k = 0; k < KC; k++) {
            float xv[8];
#pragma unroll
            for (int i = 0; i < 8; i++) xv[i] = sX[(rg * 8 + i) * XPAD + k];
            const float4* wp = (const float4*)(sW + (kc * KC + k) * FH + cg * 8);
            float4 wa = wp[0], wb = wp[1];
#pragma unroll
            for (int i = 0; i < 8; i++) {
                acc[i * 8 + 0] = fmaf(xv[i], wa.x, acc[i * 8 + 0]);
                acc[i * 8 + 1] = fmaf(xv[i], wa.y, acc[i * 8 + 1]);
                acc[i * 8 + 2] = fmaf(xv[i], wa.z, acc[i * 8 + 2]);
                acc[i * 8 + 3] = fmaf(xv[i], wa.w, acc[i * 8 + 3]);
                acc[i * 8 + 4] = fmaf(xv[i], wb.x, acc[i * 8 + 4]);
                acc[i * 8 + 5] = fmaf(xv[i], wb.y, acc[i * 8 + 5]);
                acc[i * 8 + 6] = fmaf(xv[i], wb.z, acc[i * 8 + 6]);
                acc[i * 8 + 7] = fmaf(xv[i], wb.w, acc[i * 8 + 7]);
            }
        }
    }

#pragma unroll
    for (int i = 0; i < 8; i++) {
        int grow = row0 + rg * 8 + i;
        if (grow >= N_NODES) break;
        float s = g_inv[grow];
        H8 pk;
        pk.a = __floats2half2_rn(acc[i * 8 + 0] * s, acc[i * 8 + 1] * s);
        pk.b = __floats2half2_rn(acc[i * 8 + 2] * s, acc[i * 8 + 3] * s);
        pk.c = __floats2half2_rn(acc[i * 8 + 4] * s, acc[i * 8 + 5] * s);
        pk.d = __floats2half2_rn(acc[i * 8 + 6] * s, acc[i * 8 + 7] * s);
        ((H8*)(g_h1ph + (size_t)grow * 32))[cg] = pk;
    }
}

// gather-aggregate layer1 (fp16 payload, fp32 accum):
// a1[d] = inv[d] * (sum_in h1p[src] + h1p[d]); 16 lanes/dst, 4 halves each
__global__ void __launch_bounds__(256) k_agg1() {
    long long t = (long long)blockIdx.x * 256 + threadIdx.x;
    int d = (int)(t >> 4);
    if (d >= N_NODES) return;
    int q = (int)(t & 15);
    int cnt = g_deg[d];
    if (cnt > MAXD) cnt = MAXD;
    const int* sp = g_srcs + (size_t)d * MAXD;

    uint2 selfraw = ((const uint2*)(g_h1ph + (size_t)d * 32))[q];
    float2 f0 = __half22float2(*reinterpret_cast<__half2*>(&selfraw.x));
    float2 f1 = __half22float2(*reinterpret_cast<__half2*>(&selfraw.y));
    float4 acc = make_float4(f0.x, f0.y, f1.x, f1.y);

#pragma unroll 2
    for (int j = 0; j < cnt; j++) {
        int s = __ldg(&sp[j]);
        uint2 raw = __ldg((const uint2*)(g_h1ph + (size_t)s * 32) + q);
        float2 a = __half22float2(*reinterpret_cast<__half2*>(&raw.x));
        float2 b = __half22float2(*reinterpret_cast<__half2*>(&raw.y));
        acc.x += a.x; acc.y += a.y; acc.z += b.x; acc.w += b.y;
    }
    float w = g_inv[d];
    ((float4*)g_a1)[(size_t)d * 16 + q] =
        make_float4(acc.x * w, acc.y * w, acc.z * w, acc.w * w);
}

// ---------------- gemm2: fused transform + register-blocked 128x40, tile 8x5 ----
#define APAD 65
__global__ void __launch_bounds__(128) k_gemm2(const float* __restrict__ b1,
                                               const float* __restrict__ W2) {
    __shared__ float sW[FH * FOUT];       // 10.2KB
    __shared__ float sA[128 * APAD];      // 33.3KB
    __shared__ float sb1[FH];

    int tid = threadIdx.x;
    for (int idx = tid; idx < FH * FOUT / 4; idx += 128)
        ((float4*)sW)[idx] = ((const float4*)W2)[idx];
    if (tid < FH) sb1[tid] = b1[tid];
    __syncthreads();

    int row0 = blockIdx.x * 128;

    // stage a1 with fused bias+relu+dropout
    {
        int k4 = tid & 15;
        int rr = tid >> 4;
#pragma unroll
        for (int p = 0; p < 16; p++) {
            int r = rr + p * 8;
            int grow = row0 + r;
            float4 v = make_float4(0.f, 0.f, 0.f, 0.f);
            if (grow < N_NODES) {
                v = ((const float4*)(g_a1 + (size_t)grow * FH))[k4];
                uint32_t ib = (uint32_t)grow * FH + k4 * 4;
                float t0 = fmaxf(v.x + sb1[k4 * 4 + 0], 0.0f);
                float t1 = fmaxf(v.y + sb1[k4 * 4 + 1], 0.0f);
                float t2 = fmaxf(v.z + sb1[k4 * 4 + 2], 0.0f);
                float t3 = fmaxf(v.w + sb1[k4 * 4 + 3], 0.0f);
                v.x = keep_mask(ib + 0) ? t0 * 2.0f : 0.0f;
                v.y = keep_mask(ib + 1) ? t1 * 2.0f : 0.0f;
                v.z = keep_mask(ib + 2) ? t2 * 2.0f : 0.0f;
                v.w = keep_mask(ib + 3) ? t3 * 2.0f : 0.0f;
            }
            float* dst = sA + r * APAD + k4 * 4;
            dst[0] = v.x; dst[1] = v.y; dst[2] = v.z; dst[3] = v.w;
        }
    }
    __syncthreads();

    int cg = tid & 7;
    int rg = tid >> 3;

    float acc[40];
#pragma unroll
    for (int c = 0; c < 40; c++) acc[c] = 0.0f;

#pragma unroll 4
    for (int k = 0; k < FH; k++) {
        float xv[8];
#pragma unroll
        for (int i = 0; i < 8; i++) xv[i] = sA[(rg * 8 + i) * APAD + k];
        float wv[5];
#pragma unroll
        for (int c = 0; c < 5; c++) wv[c] = sW[k * FOUT + cg * 5 + c];
#pragma unroll
        for (int i = 0; i < 8; i++)
#pragma unroll
            for (int c = 0; c < 5; c++)
                acc[i * 5 + c] = fmaf(xv[i], wv[c], acc[i * 5 + c]);
    }

    // epilogue: h2ph = fp16(acc * inv[row]); scalar half stores (row = 40 halves)
#pragma unroll
    for (int i = 0; i < 8; i++) {
        int grow = row0 + rg * 8 + i;
        if (grow >= N_NODES) break;
        float s = g_inv[grow];
        __half* hp = (__half*)g_h2ph + (size_t)grow * FOUT + cg * 5;
#pragma unroll
        for (int c = 0; c < 5; c++)
            hp[c] = __float2half_rn(acc[i * 5 + c] * s);
    }
}

// gather-aggregate layer2 (fp16 payload): out[d] = inv[d]*(sum + self) + b2
// 10 lanes/dst, 4 halves each
__global__ void __launch_bounds__(320) k_agg2(const float* __restrict__ b2,
                                              float* __restrict__ out) {
    long long t = (long long)blockIdx.x * 320 + threadIdx.x;
    int d = (int)(t / 10);
    if (d >= N_NODES) return;
    int q = (int)(t - (long long)d * 10);
    int cnt = g_deg[d];
    if (cnt > MAXD) cnt = MAXD;
    const int* sp = g_srcs + (size_t)d * MAXD;

    uint2 selfraw = ((const uint2*)(g_h2ph + (size_t)d * 20))[q];
    float2 f0 = __half22float2(*reinterpret_cast<__half2*>(&selfraw.x));
    float2 f1 = __half22float2(*reinterpret_cast<__half2*>(&selfraw.y));
    float4 acc = make_float4(f0.x, f0.y, f1.x, f1.y);

#pragma unroll 2
    for (int j = 0; j < cnt; j++) {
        int s = __ldg(&sp[j]);
        uint2 raw = __ldg((const uint2*)(g_h2ph + (size_t)s * 20) + q);
        float2 a = __half22float2(*reinterpret_cast<__half2*>(&raw.x));
        float2 b = __half22float2(*reinterpret_cast<__half2*>(&raw.y));
        acc.x += a.x; acc.y += a.y; acc.z += b.x; acc.w += b.y;
    }
    float w = g_inv[d];
    float4 bv = ((const float4*)b2)[q];
    ((float4*)out)[(size_t)d * 10 + q] =
        make_float4(acc.x * w + bv.x, acc.y * w + bv.y,
                    acc.z * w + bv.z, acc.w * w + bv.w);
}

// ---------------- launch ----------------
extern "C" void kernel_launch(void* const* d_in, const int* in_sizes, int n_in,
                              void* d_out, int out_size) {
    const float* x  = (const float*)d_in[0];
    const void*  ei = d_in[1];
    const float* W1 = (const float*)d_in[2];
    const float* b1 = (const float*)d_in[3];
    const float* W2 = (const float*)d_in[4];
    const float* b2 = (const float*)d_in[5];
    float* out = (float*)d_out;

    k_init<<<(N_NODES + 255) / 256, 256>>>((const long long*)ei);
    k_bucket<<<(N_EDGES + 255) / 256, 256>>>(ei);
    k_inv<<<(N_NODES + 255) / 256, 256>>>();
    k_gemm1<<<(N_NODES + 127) / 128, 128>>>(x, W1);
    k_agg1<<<(int)(((long long)N_NODES * 16 + 255) / 256), 256>>>();
    k_gemm2<<<(N_NODES + 127) / 128, 128>>>(b1, W2);
    k_agg2<<<(int)(((long long)N_NODES * 10 + 319) / 320), 320>>>(b2, out);
}

// round 11
// speedup vs baseline: 2.7998x; 1.1079x over previous
#include <cuda_runtime.h>
#include <cuda_fp16.h>
#include <mma.h>
#include <cstdint>

using namespace nvcuda;

#define N_NODES 100000
#define N_EDGES 1600000
#define FIN 128
#define FH 64
#define FOUT 40
#define MAXD 64    // ELL cap; in-deg ~ Poisson(16), P(any node >= 64) < 1e-15

// ---------------- scratch (device globals; no allocs allowed) ----------------
__device__ __align__(16) __half2 g_h1ph[(size_t)N_NODES * 32]; // (x@W1)*inv, fp16, 64/row
__device__ __align__(16) __half2 g_h2ph[(size_t)N_NODES * 20]; // (a1'@W2)*inv, fp16, 40/row
__device__ __align__(16) float   g_a1[N_NODES * FH];           // aggregated (fp32, exact path)
__device__ int   g_srcs[(size_t)N_NODES * MAXD];               // ELL in-edge source lists
__device__ int   g_deg[N_NODES];
__device__ float g_inv[N_NODES];
__device__ int   g_is64;

struct alignas(16) H8 { __half2 a, b, c, d; };

// ---------------- helpers ----------------
__device__ __forceinline__ int load_idx(const void* ei, int half, int e) {
    if (g_is64) return (int)((const long long*)ei)[(size_t)half * N_EDGES + e];
    return ((const int*)ei)[(size_t)half * N_EDGES + e];
}

// Threefry-2x32, 20 rounds (JAX rotation schedule) — verified bit-exact vs ref
__device__ __forceinline__ uint2 threefry2x32(uint32_t k0, uint32_t k1,
                                              uint32_t x0, uint32_t x1) {
    uint32_t ks2 = 0x1BD11BDAu ^ k0 ^ k1;
    x0 += k0; x1 += k1;
#define TF_R(r) { x0 += x1; x1 = __funnelshift_l(x1, x1, r); x1 ^= x0; }
    TF_R(13) TF_R(15) TF_R(26) TF_R(6)
    x0 += k1;  x1 += ks2 + 1u;
    TF_R(17) TF_R(29) TF_R(16) TF_R(24)
    x0 += ks2; x1 += k0 + 2u;
    TF_R(13) TF_R(15) TF_R(26) TF_R(6)
    x0 += k0;  x1 += k1 + 3u;
    TF_R(17) TF_R(29) TF_R(16) TF_R(24)
    x0 += k1;  x1 += ks2 + 4u;
    TF_R(13) TF_R(15) TF_R(26) TF_R(6)
    x0 += ks2; x1 += k0 + 5u;
#undef TF_R
    return make_uint2(x0, x1);
}

__device__ __forceinline__ bool keep_mask(uint32_t i) {
    uint2 o = threefry2x32(0u, 42u, 0u, i);
    uint32_t bits = o.x ^ o.y;
    float u = __uint_as_float((bits >> 9) | 0x3f800000u) - 1.0f;
    return u < 0.5f;
}

// ---------------- small kernels ----------------
__global__ void k_init(const long long* ei) {
    __shared__ int s_ok;
    int i = blockIdx.x * 256 + threadIdx.x;
    if (i < N_NODES) g_deg[i] = 0;
    if (blockIdx.x == 0) {
        if (threadIdx.x == 0) s_ok = 1;
        __syncthreads();
        if (threadIdx.x < 128) {
            long long v = ei[threadIdx.x];
            if (v < 0 || v >= N_NODES) atomicAnd(&s_ok, 0);
        }
        __syncthreads();
        if (threadIdx.x == 0) g_is64 = s_ok;
    }
}

__global__ void k_bucket(const void* ei) {
    int e = blockIdx.x * 256 + threadIdx.x;
    if (e >= N_EDGES) return;
    int s = load_idx(ei, 0, e);
    int d = load_idx(ei, 1, e);
    int pos = atomicAdd(&g_deg[d], 1);
    if (pos < MAXD) g_srcs[(size_t)d * MAXD + pos] = s;
}

__global__ void k_inv() {
    int i = blockIdx.x * 256 + threadIdx.x;
    if (i < N_NODES) g_inv[i] = rsqrtf((float)g_deg[i] + 1.0f);
}

// ---------------- gemm1: fp16 tensor-core wmma, 64 rows/block ----------------
// h1ph = fp16( (x @ W1) * inv[row] );  A,B quantized fp16, fp32 accumulate
#define GX_LD 136   // halfs; multiple of 8 (16B) for wmma
#define GW_LD 72    // halfs; multiple of 8
__global__ void __launch_bounds__(128) k_gemm1(const float* __restrict__ x,
                                               const float* __restrict__ W1) {
    __shared__ __align__(16) __half sX[64 * GX_LD];   // 17408 B; reused as 64x64 f32 C (16384 B)
    __shared__ __align__(16) __half sW[FIN * GW_LD];  // 18432 B, [k][n]

    int tid = threadIdx.x;
    int wid = tid >> 5;
    int row0 = blockIdx.x * 64;

    // stage W1 [128][64] fp32 -> fp16 smem [k][n] (2048 float4 / 128 thr = 16 iters)
    for (int idx = tid; idx < FIN * FH / 4; idx += 128) {
        float4 v = ((const float4*)W1)[idx];
        int flat = idx * 4;
        int k = flat >> 6;          // /64
        int n = flat & 63;
        __half* dst = sW + k * GW_LD + n;
        dst[0] = __float2half(v.x); dst[1] = __float2half(v.y);
        dst[2] = __float2half(v.z); dst[3] = __float2half(v.w);
    }
    // stage x rows fp32 -> fp16 smem [r][k]
    for (int idx = tid; idx < 64 * FIN / 4; idx += 128) {
        int flat = idx * 4;
        int r = flat >> 7;          // /128
        int c = flat & 127;
        float4 v = make_float4(0.f, 0.f, 0.f, 0.f);
        int grow = row0 + r;
        if (grow < N_NODES)
            v = *(const float4*)(x + (size_t)grow * FIN + c);
        __half* dst = sX + r * GX_LD + c;
        dst[0] = __float2half(v.x); dst[1] = __float2half(v.y);
        dst[2] = __float2half(v.z); dst[3] = __float2half(v.w);
    }
    __syncthreads();

    // each warp: 16 rows x 64 cols (4 col tiles), k-loop 8 x 16
    wmma::fragment<wmma::accumulator, 16, 16, 16, float> fc[4];
#pragma unroll
    for (int nt = 0; nt < 4; nt++) wmma::fill_fragment(fc[nt], 0.0f);

#pragma unroll
    for (int k = 0; k < FIN; k += 16) {
        wmma::fragment<wmma::matrix_a, 16, 16, 16, __half, wmma::row_major> fa;
        wmma::load_matrix_sync(fa, sX + (wid * 16) * GX_LD + k, GX_LD);
#pragma unroll
        for (int nt = 0; nt < 4; nt++) {
            wmma::fragment<wmma::matrix_b, 16, 16, 16, __half, wmma::row_major> fb;
            wmma::load_matrix_sync(fb, sW + k * GW_LD + nt * 16, GW_LD);
            wmma::mma_sync(fc[nt], fa, fb, fc[nt]);
        }
    }

    __syncthreads();                       // done reading sX; reuse as C
    float* sC = (float*)sX;                // 64 x 64, ld 64
#pragma unroll
    for (int nt = 0; nt < 4; nt++)
        wmma::store_matrix_sync(sC + (wid * 16) * 64 + nt * 16, fc[nt], 64,
                                wmma::mem_row_major);
    __syncthreads();

    // epilogue: scale by inv[row], pack half2 -> g_h1ph. thread: row tid/2, 32-col half
    {
        int r = tid >> 1;
        int ch = (tid & 1) * 32;
        int grow = row0 + r;
        if (grow < N_NODES) {
            float s = g_inv[grow];
            const float* src = sC + r * 64 + ch;
            H8* dst = (H8*)(g_h1ph + (size_t)grow * 32) + (ch >> 3);
#pragma unroll
            for (int b = 0; b < 4; b++) {
                H8 pk;
                pk.a = __floats2half2_rn(src[b * 8 + 0] * s, src[b * 8 + 1] * s);
                pk.b = __floats2half2_rn(src[b * 8 + 2] * s, src[b * 8 + 3] * s);
                pk.c = __floats2half2_rn(src[b * 8 + 4] * s, src[b * 8 + 5] * s);
                pk.d = __floats2half2_rn(src[b * 8 + 6] * s, src[b * 8 + 7] * s);
                dst[b] = pk;
            }
        }
    }
}

// gather-aggregate layer1 (fp16 payload, fp32 accum):
// a1[d] = inv[d] * (sum_in h1p[src] + h1p[d]); 16 lanes/dst, 4 halves each
__global__ void __launch_bounds__(256) k_agg1() {
    long long t = (long long)blockIdx.x * 256 + threadIdx.x;
    int d = (int)(t >> 4);
    if (d >= N_NODES) return;
    int q = (int)(t & 15);
    int cnt = g_deg[d];
    if (cnt > MAXD) cnt = MAXD;
    const int* sp = g_srcs + (size_t)d * MAXD;

    uint2 selfraw = ((const uint2*)(g_h1ph + (size_t)d * 32))[q];
    float2 f0 = __half22float2(*reinterpret_cast<__half2*>(&selfraw.x));
    float2 f1 = __half22float2(*reinterpret_cast<__half2*>(&selfraw.y));
    float4 acc = make_float4(f0.x, f0.y, f1.x, f1.y);

#pragma unroll 2
    for (int j = 0; j < cnt; j++) {
        int s = __ldg(&sp[j]);
        uint2 raw = __ldg((const uint2*)(g_h1ph + (size_t)s * 32) + q);
        float2 a = __half22float2(*reinterpret_cast<__half2*>(&raw.x));
        float2 b = __half22float2(*reinterpret_cast<__half2*>(&raw.y));
        acc.x += a.x; acc.y += a.y; acc.z += b.x; acc.w += b.y;
    }
    float w = g_inv[d];
    ((float4*)g_a1)[(size_t)d * 16 + q] =
        make_float4(acc.x * w, acc.y * w, acc.z * w, acc.w * w);
}

// ---------------- gemm2: fused transform + register-blocked 128x40, tile 8x5 ----
#define APAD 65
__global__ void __launch_bounds__(128) k_gemm2(const float* __restrict__ b1,
                                               const float* __restrict__ W2) {
    __shared__ float sW[FH * FOUT];       // 10.2KB
    __shared__ float sA[128 * APAD];      // 33.3KB
    __shared__ float sb1[FH];

    int tid = threadIdx.x;
    for (int idx = tid; idx < FH * FOUT / 4; idx += 128)
        ((float4*)sW)[idx] = ((const float4*)W2)[idx];
    if (tid < FH) sb1[tid] = b1[tid];
    __syncthreads();

    int row0 = blockIdx.x * 128;

    // stage a1 with fused bias+relu+dropout
    {
        int k4 = tid & 15;
        int rr = tid >> 4;
#pragma unroll
        for (int p = 0; p < 16; p++) {
            int r = rr + p * 8;
            int grow = row0 + r;
            float4 v = make_float4(0.f, 0.f, 0.f, 0.f);
            if (grow < N_NODES) {
                v = ((const float4*)(g_a1 + (size_t)grow * FH))[k4];
                uint32_t ib = (uint32_t)grow * FH + k4 * 4;
                float t0 = fmaxf(v.x + sb1[k4 * 4 + 0], 0.0f);
                float t1 = fmaxf(v.y + sb1[k4 * 4 + 1], 0.0f);
                float t2 = fmaxf(v.z + sb1[k4 * 4 + 2], 0.0f);
                float t3 = fmaxf(v.w + sb1[k4 * 4 + 3], 0.0f);
                v.x = keep_mask(ib + 0) ? t0 * 2.0f : 0.0f;
                v.y = keep_mask(ib + 1) ? t1 * 2.0f : 0.0f;
                v.z = keep_mask(ib + 2) ? t2 * 2.0f : 0.0f;
                v.w = keep_mask(ib + 3) ? t3 * 2.0f : 0.0f;
            }
            float* dst = sA + r * APAD + k4 * 4;
            dst[0] = v.x; dst[1] = v.y; dst[2] = v.z; dst[3] = v.w;
        }
    }
    __syncthreads();

    int cg = tid & 7;
    int rg = tid >> 3;

    float acc[40];
#pragma unroll
    for (int c = 0; c < 40; c++) acc[c] = 0.0f;

#pragma unroll 4
    for (int k = 0; k < FH; k++) {
        float xv[8];
#pragma unroll
        for (int i = 0; i < 8; i++) xv[i] = sA[(rg * 8 + i) * APAD + k];
        float wv[5];
#pragma unroll
        for (int c = 0; c < 5; c++) wv[c] = sW[k * FOUT + cg * 5 + c];
#pragma unroll
        for (int i = 0; i < 8; i++)
#pragma unroll
            for (int c = 0; c < 5; c++)
                acc[i * 5 + c] = fmaf(xv[i], wv[c], acc[i * 5 + c]);
    }

    // epilogue: h2ph = fp16(acc * inv[row]); scalar half stores (row = 40 halves)
#pragma unroll
    for (int i = 0; i < 8; i++) {
        int grow = row0 + rg * 8 + i;
        if (grow >= N_NODES) break;
        float s = g_inv[grow];
        __half* hp = (__half*)g_h2ph + (size_t)grow * FOUT + cg * 5;
#pragma unroll
        for (int c = 0; c < 5; c++)
            hp[c] = __float2half_rn(acc[i * 5 + c] * s);
    }
}

// gather-aggregate layer2 (fp16 payload): out[d] = inv[d]*(sum + self) + b2
// 10 lanes/dst, 4 halves each
__global__ void __launch_bounds__(320) k_agg2(const float* __restrict__ b2,
                                              float* __restrict__ out) {
    long long t = (long long)blockIdx.x * 320 + threadIdx.x;
    int d = (int)(t / 10);
    if (d >= N_NODES) return;
    int q = (int)(t - (long long)d * 10);
    int cnt = g_deg[d];
    if (cnt > MAXD) cnt = MAXD;
    const int* sp = g_srcs + (size_t)d * MAXD;

    uint2 selfraw = ((const uint2*)(g_h2ph + (size_t)d * 20))[q];
    float2 f0 = __half22float2(*reinterpret_cast<__half2*>(&selfraw.x));
    float2 f1 = __half22float2(*reinterpret_cast<__half2*>(&selfraw.y));
    float4 acc = make_float4(f0.x, f0.y, f1.x, f1.y);

#pragma unroll 2
    for (int j = 0; j < cnt; j++) {
        int s = __ldg(&sp[j]);
        uint2 raw = __ldg((const uint2*)(g_h2ph + (size_t)s * 20) + q);
        float2 a = __half22float2(*reinterpret_cast<__half2*>(&raw.x));
        float2 b = __half22float2(*reinterpret_cast<__half2*>(&raw.y));
        acc.x += a.x; acc.y += a.y; acc.z += b.x; acc.w += b.y;
    }
    float w = g_inv[d];
    float4 bv = ((const float4*)b2)[q];
    ((float4*)out)[(size_t)d * 10 + q] =
        make_float4(acc.x * w + bv.x, acc.y * w + bv.y,
                    acc.z * w + bv.z, acc.w * w + bv.w);
}

// ---------------- launch ----------------
extern "C" void kernel_launch(void* const* d_in, const int* in_sizes, int n_in,
                              void* d_out, int out_size) {
    const float* x  = (const float*)d_in[0];
    const void*  ei = d_in[1];
    const float* W1 = (const float*)d_in[2];
    const float* b1 = (const float*)d_in[3];
    const float* W2 = (const float*)d_in[4];
    const float* b2 = (const float*)d_in[5];
    float* out = (float*)d_out;

    k_init<<<(N_NODES + 255) / 256, 256>>>((const long long*)ei);
    k_bucket<<<(N_EDGES + 255) / 256, 256>>>(ei);
    k_inv<<<(N_NODES + 255) / 256, 256>>>();
    k_gemm1<<<(N_NODES + 63) / 64, 128>>>(x, W1);
    k_agg1<<<(int)(((long long)N_NODES * 16 + 255) / 256), 256>>>();
    k_gemm2<<<(N_NODES + 127) / 128, 128>>>(b1, W2);
    k_agg2<<<(int)(((long long)N_NODES * 10 + 319) / 320), 320>>>(b2, out);
}

// round 13
// speedup vs baseline: 3.4397x; 1.2286x over previous
#include <cuda_runtime.h>
#include <cuda_fp16.h>
#include <mma.h>
#include <cstdint>

using namespace nvcuda;

#define N_NODES 100000
#define N_EDGES 1600000
#define FIN 128
#define FH 64
#define FOUT 40
#define MAXD 64    // ELL cap; in-deg ~ Poisson(16), P(any node >= 64) < 1e-15

// ---------------- scratch (device globals; no allocs allowed) ----------------
__device__ __align__(16) __half2 g_h1ph[(size_t)N_NODES * 32]; // (x@W1)*inv, fp16, 64/row
__device__ __align__(16) __half2 g_h2ph[(size_t)N_NODES * 20]; // (a1'@W2)*inv, fp16, 40/row
__device__ __align__(16) float   g_a1[N_NODES * FH];           // aggregated (fp32, exact path)
__device__ __align__(16) __half  g_w1h[FIN * FH];              // fp16 W1, quantized once
__device__ int   g_srcs[(size_t)N_NODES * MAXD];               // ELL in-edge source lists
__device__ int   g_deg[N_NODES];
__device__ float g_inv[N_NODES];
__device__ int   g_is64;

struct alignas(16) H8 { __half2 a, b, c, d; };

// ---------------- helpers ----------------
__device__ __forceinline__ int load_idx(const void* ei, int half, int e) {
    if (g_is64) return (int)((const long long*)ei)[(size_t)half * N_EDGES + e];
    return ((const int*)ei)[(size_t)half * N_EDGES + e];
}

// Threefry-2x32, 20 rounds (JAX rotation schedule) — verified bit-exact vs ref
__device__ __forceinline__ uint2 threefry2x32(uint32_t k0, uint32_t k1,
                                              uint32_t x0, uint32_t x1) {
    uint32_t ks2 = 0x1BD11BDAu ^ k0 ^ k1;
    x0 += k0; x1 += k1;
#define TF_R(r) { x0 += x1; x1 = __funnelshift_l(x1, x1, r); x1 ^= x0; }
    TF_R(13) TF_R(15) TF_R(26) TF_R(6)
    x0 += k1;  x1 += ks2 + 1u;
    TF_R(17) TF_R(29) TF_R(16) TF_R(24)
    x0 += ks2; x1 += k0 + 2u;
    TF_R(13) TF_R(15) TF_R(26) TF_R(6)
    x0 += k0;  x1 += k1 + 3u;
    TF_R(17) TF_R(29) TF_R(16) TF_R(24)
    x0 += k1;  x1 += ks2 + 4u;
    TF_R(13) TF_R(15) TF_R(26) TF_R(6)
    x0 += ks2; x1 += k0 + 5u;
#undef TF_R
    return make_uint2(x0, x1);
}

__device__ __forceinline__ bool keep_mask(uint32_t i) {
    uint2 o = threefry2x32(0u, 42u, 0u, i);
    uint32_t bits = o.x ^ o.y;
    float u = __uint_as_float((bits >> 9) | 0x3f800000u) - 1.0f;
    return u < 0.5f;
}

// ---------------- small kernels ----------------
__global__ void k_init(const long long* ei) {
    __shared__ int s_ok;
    int i = blockIdx.x * 256 + threadIdx.x;
    if (i < N_NODES) g_deg[i] = 0;
    if (blockIdx.x == 0) {
        if (threadIdx.x == 0) s_ok = 1;
        __syncthreads();
        if (threadIdx.x < 128) {
            long long v = ei[threadIdx.x];
            if (v < 0 || v >= N_NODES) atomicAnd(&s_ok, 0);
        }
        __syncthreads();
        if (threadIdx.x == 0) g_is64 = s_ok;
    }
}

__global__ void k_bucket(const void* ei) {
    int e = blockIdx.x * 256 + threadIdx.x;
    if (e >= N_EDGES) return;
    int s = load_idx(ei, 0, e);
    int d = load_idx(ei, 1, e);
    int pos = atomicAdd(&g_deg[d], 1);
    if (pos < MAXD) g_srcs[(size_t)d * MAXD + pos] = s;
}

__global__ void k_inv() {
    int i = blockIdx.x * 256 + threadIdx.x;
    if (i < N_NODES) g_inv[i] = rsqrtf((float)g_deg[i] + 1.0f);
}

// quantize W1 to fp16 once (8192 floats)
__global__ void k_quant_w1(const float* __restrict__ W1) {
    int idx = blockIdx.x * 256 + threadIdx.x;   // float4 index
    if (idx >= FIN * FH / 4) return;
    float4 v = ((const float4*)W1)[idx];
    __half2 h0 = __floats2half2_rn(v.x, v.y);
    __half2 h1 = __floats2half2_rn(v.z, v.w);
    ((uint2*)g_w1h)[idx] = make_uint2(*(uint32_t*)&h0, *(uint32_t*)&h1);
}

// ---------------- gemm1: fp16 wmma, 64 rows/block, 256 threads ----------------
// h1ph = fp16( (x @ W1) * inv[row] )
#define GX_LD 136   // halfs
#define GW_LD 72    // halfs
__global__ void __launch_bounds__(256) k_gemm1(const float* __restrict__ x) {
    __shared__ __align__(16) __half sX[64 * GX_LD];   // 17408 B; reused as 64x64 f32 C
    __shared__ __align__(16) __half sW[FIN * GW_LD];  // 18432 B, [k][n]

    int tid = threadIdx.x;
    int wid = tid >> 5;
    int row0 = blockIdx.x * 64;

    // stage fp16 W1 [k][n] from g_w1h: 1024 16B-chunks
    for (int idx = tid; idx < FIN * FH / 8; idx += 256) {
        uint4 v = ((const uint4*)g_w1h)[idx];
        int k = idx >> 3;
        int c = idx & 7;
        *(uint4*)(sW + k * GW_LD + c * 8) = v;
    }
    // stage x rows fp32 -> fp16 smem [r][k]
    for (int idx = tid; idx < 64 * FIN / 4; idx += 256) {
        int flat = idx * 4;
        int r = flat >> 7;
        int c = flat & 127;
        float4 v = make_float4(0.f, 0.f, 0.f, 0.f);
        int grow = row0 + r;
        if (grow < N_NODES)
            v = *(const float4*)(x + (size_t)grow * FIN + c);
        __half2 h0 = __floats2half2_rn(v.x, v.y);
        __half2 h1 = __floats2half2_rn(v.z, v.w);
        *(uint2*)(sX + r * GX_LD + c) = make_uint2(*(uint32_t*)&h0, *(uint32_t*)&h1);
    }
    __syncthreads();

    // 8 warps: row strip rs = wid&3 (16 rows), col half ct = wid>>2 (32 cols = 2 tiles)
    int rs = wid & 3;
    int ct = wid >> 2;
    wmma::fragment<wmma::accumulator, 16, 16, 16, float> fc[2];
#pragma unroll
    for (int nt = 0; nt < 2; nt++) wmma::fill_fragment(fc[nt], 0.0f);

#pragma unroll
    for (int k = 0; k < FIN; k += 16) {
        wmma::fragment<wmma::matrix_a, 16, 16, 16, __half, wmma::row_major> fa;
        wmma::load_matrix_sync(fa, sX + (rs * 16) * GX_LD + k, GX_LD);
#pragma unroll
        for (int nt = 0; nt < 2; nt++) {
            wmma::fragment<wmma::matrix_b, 16, 16, 16, __half, wmma::row_major> fb;
            wmma::load_matrix_sync(fb, sW + k * GW_LD + ct * 32 + nt * 16, GW_LD);
            wmma::mma_sync(fc[nt], fa, fb, fc[nt]);
        }
    }

    __syncthreads();                       // done reading sX; reuse as C
    float* sC = (float*)sX;                // 64 x 64, ld 64
#pragma unroll
    for (int nt = 0; nt < 2; nt++)
        wmma::store_matrix_sync(sC + (rs * 16) * 64 + ct * 32 + nt * 16, fc[nt], 64,
                                wmma::mem_row_major);
    __syncthreads();

    // epilogue: scale by inv[row], pack half2 -> g_h1ph. thread: row tid>>2, 16-col quarter
    {
        int r = tid >> 2;
        int qt = tid & 3;
        int grow = row0 + r;
        if (grow < N_NODES) {
            float s = g_inv[grow];
            const float* src = sC + r * 64 + qt * 16;
            H8* dst = (H8*)(g_h1ph + (size_t)grow * 32) + qt * 2;
#pragma unroll
            for (int b = 0; b < 2; b++) {
                H8 pk;
                pk.a = __floats2half2_rn(src[b * 8 + 0] * s, src[b * 8 + 1] * s);
                pk.b = __floats2half2_rn(src[b * 8 + 2] * s, src[b * 8 + 3] * s);
                pk.c = __floats2half2_rn(src[b * 8 + 4] * s, src[b * 8 + 5] * s);
                pk.d = __floats2half2_rn(src[b * 8 + 6] * s, src[b * 8 + 7] * s);
                dst[b] = pk;
            }
        }
    }
}

// gather-aggregate layer1 (fp16 payload, fp32 accum):
// a1[d] = inv[d] * (sum_in h1p[src] + h1p[d]); 16 lanes/dst, 4 halves each
__global__ void __launch_bounds__(256) k_agg1() {
    long long t = (long long)blockIdx.x * 256 + threadIdx.x;
    int d = (int)(t >> 4);
    if (d >= N_NODES) return;
    int q = (int)(t & 15);
    int cnt = g_deg[d];
    if (cnt > MAXD) cnt = MAXD;
    const int* sp = g_srcs + (size_t)d * MAXD;

    uint2 selfraw = ((const uint2*)(g_h1ph + (size_t)d * 32))[q];
    float2 f0 = __half22float2(*reinterpret_cast<__half2*>(&selfraw.x));
    float2 f1 = __half22float2(*reinterpret_cast<__half2*>(&selfraw.y));
    float4 acc = make_float4(f0.x, f0.y, f1.x, f1.y);

#pragma unroll 2
    for (int j = 0; j < cnt; j++) {
        int s = __ldg(&sp[j]);
        uint2 raw = __ldg((const uint2*)(g_h1ph + (size_t)s * 32) + q);
        float2 a = __half22float2(*reinterpret_cast<__half2*>(&raw.x));
        float2 b = __half22float2(*reinterpret_cast<__half2*>(&raw.y));
        acc.x += a.x; acc.y += a.y; acc.z += b.x; acc.w += b.y;
    }
    float w = g_inv[d];
    ((float4*)g_a1)[(size_t)d * 16 + q] =
        make_float4(acc.x * w, acc.y * w, acc.z * w, acc.w * w);
}

// ---------------- gemm2: wmma fp16, 128 rows/block, fused transform ----------------
// A = dropout(relu(a1+b1)) fp16 [128][64], B = W2 fp16 [64][48 pad], C fp32 [128][48]
#define A2_LD 72    // halfs
#define W2_LD 48    // halfs
#define C2_LD 48    // floats
__global__ void __launch_bounds__(256) k_gemm2(const float* __restrict__ b1,
                                               const float* __restrict__ W2) {
    // union: phase 1 = sA (18432 B) + sW2 (6144 B) = 24576 B; phase 2 = C (24576 B)
    __shared__ __align__(16) char smem[24576];
    __half* sA  = (__half*)smem;                 // [128][A2_LD]
    __half* sW2 = (__half*)(smem + 128 * A2_LD * 2);  // [64][W2_LD]
    float*  sC  = (float*)smem;                  // [128][C2_LD]
    __shared__ float sb1[FH];

    int tid = threadIdx.x;
    int wid = tid >> 5;
    int row0 = blockIdx.x * 128;

    if (tid < FH) sb1[tid] = b1[tid];
    // stage W2 [64][40] fp32 -> fp16 [64][48], zero-pad cols 40..47
    for (int idx = tid; idx < FH * 48 / 4; idx += 256) {
        int flat = idx * 4;
        int k = flat / 48;
        int n = flat % 48;
        float4 v = make_float4(0.f, 0.f, 0.f, 0.f);
        if (n + 3 < FOUT)
            v = *(const float4*)(W2 + k * FOUT + n);   // n multiple of 4; 40%4==0
        __half2 h0 = __floats2half2_rn(v.x, v.y);
        __half2 h1 = __floats2half2_rn(v.z, v.w);
        *(uint2*)(sW2 + k * W2_LD + n) = make_uint2(*(uint32_t*)&h0, *(uint32_t*)&h1);
    }
    __syncthreads();   // sb1 ready before transform

    // stage a1 with fused bias+relu+dropout -> fp16 sA
    for (int idx = tid; idx < 128 * FH / 4; idx += 256) {
        int flat = idx * 4;
        int r = flat >> 6;
        int c = flat & 63;
        int grow = row0 + r;
        float4 v = make_float4(0.f, 0.f, 0.f, 0.f);
        if (grow < N_NODES) {
            v = *(const float4*)(g_a1 + (size_t)grow * FH + c);
            uint32_t ib = (uint32_t)grow * FH + c;
            float t0 = fmaxf(v.x + sb1[c + 0], 0.0f);
            float t1 = fmaxf(v.y + sb1[c + 1], 0.0f);
            float t2 = fmaxf(v.z + sb1[c + 2], 0.0f);
            float t3 = fmaxf(v.w + sb1[c + 3], 0.0f);
            v.x = keep_mask(ib + 0) ? t0 * 2.0f : 0.0f;
            v.y = keep_mask(ib + 1) ? t1 * 2.0f : 0.0f;
            v.z = keep_mask(ib + 2) ? t2 * 2.0f : 0.0f;
            v.w = keep_mask(ib + 3) ? t3 * 2.0f : 0.0f;
        }
        __half2 h0 = __floats2half2_rn(v.x, v.y);
        __half2 h1 = __floats2half2_rn(v.z, v.w);
        *(uint2*)(sA + r * A2_LD + c) = make_uint2(*(uint32_t*)&h0, *(uint32_t*)&h1);
    }
    __syncthreads();

    // 8 warps: warp w = row strip w (16 rows) x 48 cols (3 tiles)
    wmma::fragment<wmma::accumulator, 16, 16, 16, float> fc[3];
#pragma unroll
    for (int nt = 0; nt < 3; nt++) wmma::fill_fragment(fc[nt], 0.0f);

#pragma unroll
    for (int k = 0; k < FH; k += 16) {
        wmma::fragment<wmma::matrix_a, 16, 16, 16, __half, wmma::row_major> fa;
        wmma::load_matrix_sync(fa, sA + (wid * 16) * A2_LD + k, A2_LD);
#pragma unroll
        for (int nt = 0; nt < 3; nt++) {
            wmma::fragment<wmma::matrix_b, 16, 16, 16, __half, wmma::row_major> fb;
            wmma::load_matrix_sync(fb, sW2 + k * W2_LD + nt * 16, W2_LD);
            wmma::mma_sync(fc[nt], fa, fb, fc[nt]);
        }
    }

    __syncthreads();   // done with sA/sW2; reuse as C
#pragma unroll
    for (int nt = 0; nt < 3; nt++)
        wmma::store_matrix_sync(sC + (wid * 16) * C2_LD + nt * 16, fc[nt], C2_LD,
                                wmma::mem_row_major);
    __syncthreads();

    // epilogue: h2ph = fp16(C * inv[row]), first 40 cols. thread: row tid>>1, half tid&1
    {
        int r = tid >> 1;
        int hh = tid & 1;          // cols hh*20 .. +19
        int grow = row0 + r;
        if (grow < N_NODES) {
            float s = g_inv[grow];
            const float* src = sC + r * C2_LD + hh * 20;
            uint2* dst = (uint2*)((__half*)g_h2ph + (size_t)grow * FOUT + hh * 20);
#pragma unroll
            for (int b = 0; b < 5; b++) {
                __half2 h0 = __floats2half2_rn(src[b * 4 + 0] * s, src[b * 4 + 1] * s);
                __half2 h1 = __floats2half2_rn(src[b * 4 + 2] * s, src[b * 4 + 3] * s);
                dst[b] = make_uint2(*(uint32_t*)&h0, *(uint32_t*)&h1);
            }
        }
    }
}

// gather-aggregate layer2 (fp16 payload): out[d] = inv[d]*(sum + self) + b2
// 10 lanes/dst, 4 halves each
__global__ void __launch_bounds__(320) k_agg2(const float* __restrict__ b2,
                                              float* __restrict__ out) {
    long long t = (long long)blockIdx.x * 320 + threadIdx.x;
    int d = (int)(t / 10);
    if (d >= N_NODES) return;
    int q = (int)(t - (long long)d * 10);
    int cnt = g_deg[d];
    if (cnt > MAXD) cnt = MAXD;
    const int* sp = g_srcs + (size_t)d * MAXD;

    uint2 selfraw = ((const uint2*)(g_h2ph + (size_t)d * 20))[q];
    float2 f0 = __half22float2(*reinterpret_cast<__half2*>(&selfraw.x));
    float2 f1 = __half22float2(*reinterpret_cast<__half2*>(&selfraw.y));
    float4 acc = make_float4(f0.x, f0.y, f1.x, f1.y);

#pragma unroll 2
    for (int j = 0; j < cnt; j++) {
        int s = __ldg(&sp[j]);
        uint2 raw = __ldg((const uint2*)(g_h2ph + (size_t)s * 20) + q);
        float2 a = __half22float2(*reinterpret_cast<__half2*>(&raw.x));
        float2 b = __half22float2(*reinterpret_cast<__half2*>(&raw.y));
        acc.x += a.x; acc.y += a.y; acc.z += b.x; acc.w += b.y;
    }
    float w = g_inv[d];
    float4 bv = ((const float4*)b2)[q];
    ((float4*)out)[(size_t)d * 10 + q] =
        make_float4(acc.x * w + bv.x, acc.y * w + bv.y,
                    acc.z * w + bv.z, acc.w * w + bv.w);
}

// ---------------- launch ----------------
extern "C" void kernel_launch(void* const* d_in, const int* in_sizes, int n_in,
                              void* d_out, int out_size) {
    const float* x  = (const float*)d_in[0];
    const void*  ei = d_in[1];
    const float* W1 = (const float*)d_in[2];
    const float* b1 = (const float*)d_in[3];
    const float* W2 = (const float*)d_in[4];
    const float* b2 = (const float*)d_in[5];
    float* out = (float*)d_out;

    k_init<<<(N_NODES + 255) / 256, 256>>>((const long long*)ei);
    k_bucket<<<(N_EDGES + 255) / 256, 256>>>(ei);
    k_inv<<<(N_NODES + 255) / 256, 256>>>();
    k_quant_w1<<<(FIN * FH / 4 + 255) / 256, 256>>>(W1);
    k_gemm1<<<(N_NODES + 63) / 64, 256>>>(x);
    k_agg1<<<(int)(((long long)N_NODES * 16 + 255) / 256), 256>>>();
    k_gemm2<<<(N_NODES + 127) / 128, 256>>>(b1, W2);
    k_agg2<<<(int)(((long long)N_NODES * 10 + 319) / 320), 320>>>(b2, out);
}

// round 14
// speedup vs baseline: 3.6396x; 1.0581x over previous
#include <cuda_runtime.h>
#include <cuda_fp16.h>
#include <mma.h>
#include <cstdint>

using namespace nvcuda;

#define N_NODES 100000
#define N_EDGES 1600000
#define FIN 128
#define FH 64
#define FOUT 40
#define MAXD 64    // ELL cap; in-deg ~ Poisson(16), P(any node >= 64) < 1e-15

// ---------------- scratch (device globals; no allocs allowed) ----------------
__device__ __align__(16) __half2 g_h1ph[(size_t)N_NODES * 32]; // (x@W1)*inv, fp16
__device__ __align__(16) __half2 g_h2ph[(size_t)N_NODES * 20]; // (a1'@W2)*inv, fp16
__device__ __align__(16) __half  g_a1h[(size_t)N_NODES * FH];  // dropout(relu(a1+b1)), fp16
__device__ __align__(16) __half  g_w1h[FIN * FH];              // fp16 W1, quantized once
__device__ int   g_srcs[(size_t)N_NODES * MAXD];               // ELL in-edge source lists
__device__ int   g_deg[N_NODES];
__device__ float g_inv[N_NODES];
__device__ int   g_is64;

struct alignas(16) H8 { __half2 a, b, c, d; };

// ---------------- helpers ----------------
__device__ __forceinline__ int load_idx(const void* ei, int half, int e) {
    if (g_is64) return (int)((const long long*)ei)[(size_t)half * N_EDGES + e];
    return ((const int*)ei)[(size_t)half * N_EDGES + e];
}

// Threefry-2x32, 20 rounds (JAX rotation schedule) — verified bit-exact vs ref
__device__ __forceinline__ uint2 threefry2x32(uint32_t k0, uint32_t k1,
                                              uint32_t x0, uint32_t x1) {
    uint32_t ks2 = 0x1BD11BDAu ^ k0 ^ k1;
    x0 += k0; x1 += k1;
#define TF_R(r) { x0 += x1; x1 = __funnelshift_l(x1, x1, r); x1 ^= x0; }
    TF_R(13) TF_R(15) TF_R(26) TF_R(6)
    x0 += k1;  x1 += ks2 + 1u;
    TF_R(17) TF_R(29) TF_R(16) TF_R(24)
    x0 += ks2; x1 += k0 + 2u;
    TF_R(13) TF_R(15) TF_R(26) TF_R(6)
    x0 += k0;  x1 += k1 + 3u;
    TF_R(17) TF_R(29) TF_R(16) TF_R(24)
    x0 += k1;  x1 += ks2 + 4u;
    TF_R(13) TF_R(15) TF_R(26) TF_R(6)
    x0 += ks2; x1 += k0 + 5u;
#undef TF_R
    return make_uint2(x0, x1);
}

__device__ __forceinline__ bool keep_mask(uint32_t i) {
    uint2 o = threefry2x32(0u, 42u, 0u, i);
    uint32_t bits = o.x ^ o.y;
    float u = __uint_as_float((bits >> 9) | 0x3f800000u) - 1.0f;
    return u < 0.5f;
}

__device__ __forceinline__ float4 h4_to_f4(uint2 raw) {
    float2 a = __half22float2(*reinterpret_cast<__half2*>(&raw.x));
    float2 b = __half22float2(*reinterpret_cast<__half2*>(&raw.y));
    return make_float4(a.x, a.y, b.x, b.y);
}

// ---------------- small kernels ----------------
__global__ void k_init(const long long* ei) {
    __shared__ int s_ok;
    int i = blockIdx.x * 256 + threadIdx.x;
    if (i < N_NODES) g_deg[i] = 0;
    if (blockIdx.x == 0) {
        if (threadIdx.x == 0) s_ok = 1;
        __syncthreads();
        if (threadIdx.x < 128) {
            long long v = ei[threadIdx.x];
            if (v < 0 || v >= N_NODES) atomicAnd(&s_ok, 0);
        }
        __syncthreads();
        if (threadIdx.x == 0) g_is64 = s_ok;
    }
}

__global__ void k_bucket(const void* ei) {
    int e = blockIdx.x * 256 + threadIdx.x;
    if (e >= N_EDGES) return;
    int s = load_idx(ei, 0, e);
    int d = load_idx(ei, 1, e);
    int pos = atomicAdd(&g_deg[d], 1);
    if (pos < MAXD) g_srcs[(size_t)d * MAXD + pos] = s;
}

// inv = rsqrt(deg+1); also quantize W1 to fp16 (merged independent work)
__global__ void k_inv_quant(const float* __restrict__ W1) {
    int i = blockIdx.x * 256 + threadIdx.x;
    if (i < N_NODES) g_inv[i] = rsqrtf((float)g_deg[i] + 1.0f);
    if (i < FIN * FH / 4) {
        float4 v = ((const float4*)W1)[i];
        __half2 h0 = __floats2half2_rn(v.x, v.y);
        __half2 h1 = __floats2half2_rn(v.z, v.w);
        ((uint2*)g_w1h)[i] = make_uint2(*(uint32_t*)&h0, *(uint32_t*)&h1);
    }
}

// ---------------- gemm1: fp16 wmma, 64 rows/block, 256 threads ----------------
// h1ph = fp16( (x @ W1) * inv[row] )
#define GX_LD 136   // halfs
#define GW_LD 72    // halfs
__global__ void __launch_bounds__(256) k_gemm1(const float* __restrict__ x) {
    __shared__ __align__(16) __half sX[64 * GX_LD];   // 17408 B; reused as 64x64 f32 C
    __shared__ __align__(16) __half sW[FIN * GW_LD];  // 18432 B, [k][n]

    int tid = threadIdx.x;
    int wid = tid >> 5;
    int row0 = blockIdx.x * 64;

    // stage fp16 W1 [k][n] from g_w1h: 1024 16B-chunks
    for (int idx = tid; idx < FIN * FH / 8; idx += 256) {
        uint4 v = ((const uint4*)g_w1h)[idx];
        int k = idx >> 3;
        int c = idx & 7;
        *(uint4*)(sW + k * GW_LD + c * 8) = v;
    }
    // stage x rows fp32 -> fp16 smem [r][k]
    for (int idx = tid; idx < 64 * FIN / 4; idx += 256) {
        int flat = idx * 4;
        int r = flat >> 7;
        int c = flat & 127;
        float4 v = make_float4(0.f, 0.f, 0.f, 0.f);
        int grow = row0 + r;
        if (grow < N_NODES)
            v = *(const float4*)(x + (size_t)grow * FIN + c);
        __half2 h0 = __floats2half2_rn(v.x, v.y);
        __half2 h1 = __floats2half2_rn(v.z, v.w);
        *(uint2*)(sX + r * GX_LD + c) = make_uint2(*(uint32_t*)&h0, *(uint32_t*)&h1);
    }
    __syncthreads();

    int rs = wid & 3;
    int ct = wid >> 2;
    wmma::fragment<wmma::accumulator, 16, 16, 16, float> fc[2];
#pragma unroll
    for (int nt = 0; nt < 2; nt++) wmma::fill_fragment(fc[nt], 0.0f);

#pragma unroll
    for (int k = 0; k < FIN; k += 16) {
        wmma::fragment<wmma::matrix_a, 16, 16, 16, __half, wmma::row_major> fa;
        wmma::load_matrix_sync(fa, sX + (rs * 16) * GX_LD + k, GX_LD);
#pragma unroll
        for (int nt = 0; nt < 2; nt++) {
            wmma::fragment<wmma::matrix_b, 16, 16, 16, __half, wmma::row_major> fb;
            wmma::load_matrix_sync(fb, sW + k * GW_LD + ct * 32 + nt * 16, GW_LD);
            wmma::mma_sync(fc[nt], fa, fb, fc[nt]);
        }
    }

    __syncthreads();                       // done reading sX; reuse as C
    float* sC = (float*)sX;                // 64 x 64, ld 64
#pragma unroll
    for (int nt = 0; nt < 2; nt++)
        wmma::store_matrix_sync(sC + (rs * 16) * 64 + ct * 32 + nt * 16, fc[nt], 64,
                                wmma::mem_row_major);
    __syncthreads();

    // epilogue: scale by inv[row], pack half2 -> g_h1ph
    {
        int r = tid >> 2;
        int qt = tid & 3;
        int grow = row0 + r;
        if (grow < N_NODES) {
            float s = g_inv[grow];
            const float* src = sC + r * 64 + qt * 16;
            H8* dst = (H8*)(g_h1ph + (size_t)grow * 32) + qt * 2;
#pragma unroll
            for (int b = 0; b < 2; b++) {
                H8 pk;
                pk.a = __floats2half2_rn(src[b * 8 + 0] * s, src[b * 8 + 1] * s);
                pk.b = __floats2half2_rn(src[b * 8 + 2] * s, src[b * 8 + 3] * s);
                pk.c = __floats2half2_rn(src[b * 8 + 4] * s, src[b * 8 + 5] * s);
                pk.d = __floats2half2_rn(src[b * 8 + 6] * s, src[b * 8 + 7] * s);
                dst[b] = pk;
            }
        }
    }
}

// gather-aggregate layer1 + fused transform:
// a1 = inv[d]*(sum_in h1p[src] + h1p[d]);  a1h = fp16(dropout(relu(a1 + b1)))
// 16 lanes/dst, 4 halves each; 4-wide load batching for MLP
__global__ void __launch_bounds__(256) k_agg1(const float* __restrict__ b1) {
    long long t = (long long)blockIdx.x * 256 + threadIdx.x;
    int d = (int)(t >> 4);
    if (d >= N_NODES) return;
    int q = (int)(t & 15);
    int cnt = g_deg[d];
    if (cnt > MAXD) cnt = MAXD;
    const int* sp = g_srcs + (size_t)d * MAXD;

    float4 acc = h4_to_f4(((const uint2*)(g_h1ph + (size_t)d * 32))[q]);   // self

    int j = 0;
    for (; j + 4 <= cnt; j += 4) {
        int s0 = __ldg(&sp[j + 0]);
        int s1 = __ldg(&sp[j + 1]);
        int s2 = __ldg(&sp[j + 2]);
        int s3 = __ldg(&sp[j + 3]);
        uint2 r0 = __ldg((const uint2*)(g_h1ph + (size_t)s0 * 32) + q);
        uint2 r1 = __ldg((const uint2*)(g_h1ph + (size_t)s1 * 32) + q);
        uint2 r2 = __ldg((const uint2*)(g_h1ph + (size_t)s2 * 32) + q);
        uint2 r3 = __ldg((const uint2*)(g_h1ph + (size_t)s3 * 32) + q);
        float4 v0 = h4_to_f4(r0), v1 = h4_to_f4(r1), v2 = h4_to_f4(r2), v3 = h4_to_f4(r3);
        acc.x += (v0.x + v1.x) + (v2.x + v3.x);
        acc.y += (v0.y + v1.y) + (v2.y + v3.y);
        acc.z += (v0.z + v1.z) + (v2.z + v3.z);
        acc.w += (v0.w + v1.w) + (v2.w + v3.w);
    }
    for (; j < cnt; j++) {
        int s = __ldg(&sp[j]);
        float4 v = h4_to_f4(__ldg((const uint2*)(g_h1ph + (size_t)s * 32) + q));
        acc.x += v.x; acc.y += v.y; acc.z += v.z; acc.w += v.w;
    }

    float w = g_inv[d];
    int c0 = q * 4;
    uint32_t ib = (uint32_t)d * FH + c0;
    float t0 = fmaxf(acc.x * w + __ldg(&b1[c0 + 0]), 0.0f);
    float t1 = fmaxf(acc.y * w + __ldg(&b1[c0 + 1]), 0.0f);
    float t2 = fmaxf(acc.z * w + __ldg(&b1[c0 + 2]), 0.0f);
    float t3 = fmaxf(acc.w * w + __ldg(&b1[c0 + 3]), 0.0f);
    t0 = keep_mask(ib + 0) ? t0 * 2.0f : 0.0f;
    t1 = keep_mask(ib + 1) ? t1 * 2.0f : 0.0f;
    t2 = keep_mask(ib + 2) ? t2 * 2.0f : 0.0f;
    t3 = keep_mask(ib + 3) ? t3 * 2.0f : 0.0f;
    __half2 h0 = __floats2half2_rn(t0, t1);
    __half2 h1 = __floats2half2_rn(t2, t3);
    *(uint2*)(g_a1h + (size_t)d * FH + c0) = make_uint2(*(uint32_t*)&h0, *(uint32_t*)&h1);
}

// ---------------- gemm2: wmma fp16, 128 rows/block; A pre-transformed in agg1 ----
#define A2_LD 72    // halfs
#define W2_LD 48    // halfs
#define C2_LD 48    // floats
__global__ void __launch_bounds__(256) k_gemm2(const float* __restrict__ W2) {
    // union: phase 1 = sA (18432 B) + sW2 (6144 B); phase 2 = C (24576 B)
    __shared__ __align__(16) char smem[24576];
    __half* sA  = (__half*)smem;                      // [128][A2_LD]
    __half* sW2 = (__half*)(smem + 128 * A2_LD * 2);  // [64][W2_LD]
    float*  sC  = (float*)smem;                       // [128][C2_LD]

    int tid = threadIdx.x;
    int wid = tid >> 5;
    int row0 = blockIdx.x * 128;

    // stage W2 [64][40] fp32 -> fp16 [64][48], zero-pad cols 40..47
    for (int idx = tid; idx < FH * 48 / 4; idx += 256) {
        int flat = idx * 4;
        int k = flat / 48;
        int n = flat % 48;
        float4 v = make_float4(0.f, 0.f, 0.f, 0.f);
        if (n + 3 < FOUT)
            v = *(const float4*)(W2 + k * FOUT + n);
        __half2 h0 = __floats2half2_rn(v.x, v.y);
        __half2 h1 = __floats2half2_rn(v.z, v.w);
        *(uint2*)(sW2 + k * W2_LD + n) = make_uint2(*(uint32_t*)&h0, *(uint32_t*)&h1);
    }
    // stage pre-transformed fp16 A rows (uint4 = 8 halves)
    for (int idx = tid; idx < 128 * FH / 8; idx += 256) {
        int r = idx >> 3;
        int c = (idx & 7) * 8;
        int grow = row0 + r;
        uint4 v = make_uint4(0u, 0u, 0u, 0u);
        if (grow < N_NODES)
            v = *(const uint4*)(g_a1h + (size_t)grow * FH + c);
        *(uint4*)(sA + r * A2_LD + c) = v;
    }
    __syncthreads();

    // 8 warps: warp w = row strip w (16 rows) x 48 cols (3 tiles)
    wmma::fragment<wmma::accumulator, 16, 16, 16, float> fc[3];
#pragma unroll
    for (int nt = 0; nt < 3; nt++) wmma::fill_fragment(fc[nt], 0.0f);

#pragma unroll
    for (int k = 0; k < FH; k += 16) {
        wmma::fragment<wmma::matrix_a, 16, 16, 16, __half, wmma::row_major> fa;
        wmma::load_matrix_sync(fa, sA + (wid * 16) * A2_LD + k, A2_LD);
#pragma unroll
        for (int nt = 0; nt < 3; nt++) {
            wmma::fragment<wmma::matrix_b, 16, 16, 16, __half, wmma::row_major> fb;
            wmma::load_matrix_sync(fb, sW2 + k * W2_LD + nt * 16, W2_LD);
            wmma::mma_sync(fc[nt], fa, fb, fc[nt]);
        }
    }

    __syncthreads();   // done with sA/sW2; reuse as C
#pragma unroll
    for (int nt = 0; nt < 3; nt++)
        wmma::store_matrix_sync(sC + (wid * 16) * C2_LD + nt * 16, fc[nt], C2_LD,
                                wmma::mem_row_major);
    __syncthreads();

    // epilogue: h2ph = fp16(C * inv[row]), first 40 cols
    {
        int r = tid >> 1;
        int hh = tid & 1;          // cols hh*20 .. +19
        int grow = row0 + r;
        if (grow < N_NODES) {
            float s = g_inv[grow];
            const float* src = sC + r * C2_LD + hh * 20;
            uint2* dst = (uint2*)((__half*)g_h2ph + (size_t)grow * FOUT + hh * 20);
#pragma unroll
            for (int b = 0; b < 5; b++) {
                __half2 h0 = __floats2half2_rn(src[b * 4 + 0] * s, src[b * 4 + 1] * s);
                __half2 h1 = __floats2half2_rn(src[b * 4 + 2] * s, src[b * 4 + 3] * s);
                dst[b] = make_uint2(*(uint32_t*)&h0, *(uint32_t*)&h1);
            }
        }
    }
}

// gather-aggregate layer2: out[d] = inv[d]*(sum + self) + b2; 4-wide batching
__global__ void __launch_bounds__(320) k_agg2(const float* __restrict__ b2,
                                              float* __restrict__ out) {
    long long t = (long long)blockIdx.x * 320 + threadIdx.x;
    int d = (int)(t / 10);
    if (d >= N_NODES) return;
    int q = (int)(t - (long long)d * 10);
    int cnt = g_deg[d];
    if (cnt > MAXD) cnt = MAXD;
    const int* sp = g_srcs + (size_t)d * MAXD;

    float4 acc = h4_to_f4(((const uint2*)(g_h2ph + (size_t)d * 20))[q]);   // self

    int j = 0;
    for (; j + 4 <= cnt; j += 4) {
        int s0 = __ldg(&sp[j + 0]);
        int s1 = __ldg(&sp[j + 1]);
        int s2 = __ldg(&sp[j + 2]);
        int s3 = __ldg(&sp[j + 3]);
        uint2 r0 = __ldg((const uint2*)(g_h2ph + (size_t)s0 * 20) + q);
        uint2 r1 = __ldg((const uint2*)(g_h2ph + (size_t)s1 * 20) + q);
        uint2 r2 = __ldg((const uint2*)(g_h2ph + (size_t)s2 * 20) + q);
        uint2 r3 = __ldg((const uint2*)(g_h2ph + (size_t)s3 * 20) + q);
        float4 v0 = h4_to_f4(r0), v1 = h4_to_f4(r1), v2 = h4_to_f4(r2), v3 = h4_to_f4(r3);
        acc.x += (v0.x + v1.x) + (v2.x + v3.x);
        acc.y += (v0.y + v1.y) + (v2.y + v3.y);
        acc.z += (v0.z + v1.z) + (v2.z + v3.z);
        acc.w += (v0.w + v1.w) + (v2.w + v3.w);
    }
    for (; j < cnt; j++) {
        int s = __ldg(&sp[j]);
        float4 v = h4_to_f4(__ldg((const uint2*)(g_h2ph + (size_t)s * 20) + q));
        acc.x += v.x; acc.y += v.y; acc.z += v.z; acc.w += v.w;
    }

    float w = g_inv[d];
    float4 bv = ((const float4*)b2)[q];
    ((float4*)out)[(size_t)d * 10 + q] =
        make_float4(acc.x * w + bv.x, acc.y * w + bv.y,
                    acc.z * w + bv.z, acc.w * w + bv.w);
}

// ---------------- launch ----------------
extern "C" void kernel_launch(void* const* d_in, const int* in_sizes, int n_in,
                              void* d_out, int out_size) {
    const float* x  = (const float*)d_in[0];
    const void*  ei = d_in[1];
    const float* W1 = (const float*)d_in[2];
    const float* b1 = (const float*)d_in[3];
    const float* W2 = (const float*)d_in[4];
    const float* b2 = (const float*)d_in[5];
    float* out = (float*)d_out;

    k_init<<<(N_NODES + 255) / 256, 256>>>((const long long*)ei);
    k_bucket<<<(N_EDGES + 255) / 256, 256>>>(ei);
    k_inv_quant<<<(N_NODES + 255) / 256, 256>>>(W1);
    k_gemm1<<<(N_NODES + 63) / 64, 256>>>(x);
    k_agg1<<<(int)(((long long)N_NODES * 16 + 255) / 256), 256>>>(b1);
    k_gemm2<<<(N_NODES + 127) / 128, 256>>>(W2);
    k_agg2<<<(int)(((long long)N_NODES * 10 + 319) / 320), 320>>>(b2, out);
}